// round 7
// baseline (speedup 1.0000x reference)
#include <cuda_runtime.h>
#include <math.h>

// ---------------- problem constants ----------------
constexpr int N_NODES = 10000;
constexpr int N_EDGES = 160000;
constexpr int B       = 8;
constexpr int T_IN    = 12;
constexpr int HP      = 64;
constexpr int HV      = 32;
constexpr int CDIM    = 2 * HP + 1;   // 129
constexpr int NB      = N_NODES * B;  // 80000
constexpr int EB      = N_EDGES * B;  // 1280000

// ---------------- device scratch (static; no allocation) ----------------
__device__ float4 g_node[NB];     // per (node,b): P, R, S, Q
__device__ float  g_att[EB];      // ex = exp(a)
__device__ float  g_dsum[EB];     // sum_k diff*feature[src]
__device__ float  g_den[NB];      // softmax denominator
__device__ float  g_gw[CDIM];     // ln2_g * attn_w
__device__ float  g_GC[2];        // [0]=sum(g*w), [1]=sum(b*w)
__device__ float  g_xv[2 * EB];   // [0..EB): x_up ; [EB..2EB): x_dn

// ---------------- prep: gw = ln2_g*attn_w; G = sum(gw); C = sum(ln2_b*attn_w) --------
__global__ void prep_kernel(const float* __restrict__ ln2g,
                            const float* __restrict__ ln2b,
                            const float* __restrict__ attnw) {
    __shared__ float sG[256];
    __shared__ float sC[256];
    int t = threadIdx.x;
    float gv = 0.f, cv = 0.f;
    if (t < CDIM) {
        float w = attnw[t];
        gv = ln2g[t] * w;
        cv = ln2b[t] * w;
        g_gw[t] = gv;
    }
    sG[t] = gv; sC[t] = cv;
    __syncthreads();
    for (int s = 128; s > 0; s >>= 1) {
        if (t < s) { sG[t] += sG[t + s]; sC[t] += sC[t + s]; }
        __syncthreads();
    }
    if (t == 0) { g_GC[0] = sG[0]; g_GC[1] = sC[0]; }
}

// ---------------- init: zero pred, den ----------------
__global__ void init_kernel(float* __restrict__ out) {
    int t = blockIdx.x * blockDim.x + threadIdx.x;
    if (t < NB) {
        out[t]   = 0.f;
        g_den[t] = 0.f;
    }
}

// ---------------- node kernel: fold z into (P,R,S,Q) ----------------
__global__ __launch_bounds__(128)
void node_kernel(const float* __restrict__ feat,
                 const float* __restrict__ fcw) {
    __shared__ float sw[HP * T_IN];   // 768
    __shared__ float sgw[2 * HP];     // 128
    int tid = threadIdx.x;
    for (int i = tid; i < HP * T_IN; i += blockDim.x) sw[i]  = fcw[i];
    for (int i = tid; i < 2 * HP;    i += blockDim.x) sgw[i] = g_gw[i];
    __syncthreads();

    int t = blockIdx.x * blockDim.x + tid;
    if (t >= NB) return;

    float fr[T_IN];
    {
        const float4* f4 = reinterpret_cast<const float4*>(feat) + (size_t)t * 3;
        float4 a0 = f4[0], a1 = f4[1], a2 = f4[2];
        fr[0]=a0.x; fr[1]=a0.y; fr[2]=a0.z;  fr[3]=a0.w;
        fr[4]=a1.x; fr[5]=a1.y; fr[6]=a1.z;  fr[7]=a1.w;
        fr[8]=a2.x; fr[9]=a2.y; fr[10]=a2.z; fr[11]=a2.w;
    }

    float P = 0.f, R = 0.f, S = 0.f, Q = 0.f;
#pragma unroll
    for (int h = 0; h < HP; ++h) {
        float z = 0.f;
#pragma unroll
        for (int k = 0; k < T_IN; ++k) z = fmaf(sw[h * T_IN + k], fr[k], z);
        P = fmaf(z, sgw[h], P);
        R = fmaf(z, sgw[HP + h], R);
        S += z;
        Q = fmaf(z, z, Q);
    }
    g_node[t] = make_float4(P, R, S, Q);
}

// ---------------- velocity kernel: 1 thread = 1 (edge,batch) item ----------------
// sigmoid(w2 . relu(LN(W1 in + b1)) + b2); register budget: 3 blocks/SM
__global__ __launch_bounds__(256, 3)
void vel_kernel(const float* __restrict__ inp,
                const float* __restrict__ w1, const float* __restrict__ b1,
                const float* __restrict__ lg, const float* __restrict__ lb,
                const float* __restrict__ w2, const float* __restrict__ b2p,
                float* __restrict__ outp) {
    __shared__ float4 sw[HV * 3];    // weight rows, 3 float4 each (1.5 KB)
    __shared__ float4 se[HV];        // (b1, lg, lb, w2) per hidden unit
    __shared__ float  sb2;
    int tid = threadIdx.x;
    if (tid < HV * 3) sw[tid] = reinterpret_cast<const float4*>(w1)[tid];
    if (tid >= 128 && tid < 128 + HV) {
        int j = tid - 128;
        se[j] = make_float4(b1[j], lg[j], lb[j], w2[j]);
    }
    if (tid == 224) sb2 = b2p[0];
    __syncthreads();

    int t = blockIdx.x * 256 + tid;   // item in [0, EB)
    const float4* f4 = reinterpret_cast<const float4*>(inp) + (size_t)t * 3;
    float4 i0 = f4[0], i1 = f4[1], i2 = f4[2];

    float h[HV];
    float sum = 0.f, q = 0.f;
#pragma unroll
    for (int j = 0; j < HV; ++j) {
        float4 wa = sw[3 * j], wb = sw[3 * j + 1], wc = sw[3 * j + 2];
        float a = se[j].x;
        a = fmaf(wa.x, i0.x, a); a = fmaf(wa.y, i0.y, a);
        a = fmaf(wa.z, i0.z, a); a = fmaf(wa.w, i0.w, a);
        a = fmaf(wb.x, i1.x, a); a = fmaf(wb.y, i1.y, a);
        a = fmaf(wb.z, i1.z, a); a = fmaf(wb.w, i1.w, a);
        a = fmaf(wc.x, i2.x, a); a = fmaf(wc.y, i2.y, a);
        a = fmaf(wc.z, i2.z, a); a = fmaf(wc.w, i2.w, a);
        h[j] = a;
        sum += a;
        q = fmaf(a, a, q);
    }
    float m   = sum * (1.0f / HV);
    float var = fmaf(-m, m, q * (1.0f / HV));
    float inv = rsqrtf(var + 1e-5f);
    float sh  = -m * inv;            // y = (h*inv + sh)*lg + lb

    float s = sb2;
#pragma unroll
    for (int j = 0; j < HV; ++j) {
        float4 e = se[j];
        float y = fmaf(fmaf(h[j], inv, sh), e.y, e.z);
        y = fmaxf(y, 0.f);
        s = fmaf(y, e.w, s);
    }
    outp[t] = __fdividef(1.0f, 1.0f + __expf(-s));
}

// ---------------- edge attention + diffusion (softmax numerator + den) -------------
__global__ __launch_bounds__(256)
void edgeA_kernel(const float* __restrict__ dist,
                  const float* __restrict__ alpha,
                  const float* __restrict__ feat,
                  const int* __restrict__ src,
                  const int* __restrict__ dst,
                  const float* __restrict__ l3w,
                  const float* __restrict__ l3b) {
    __shared__ float c[7];
    if (threadIdx.x == 0) {
        c[0] = l3w[0]; c[1] = l3w[1]; c[2] = l3w[2]; c[3] = l3b[0];
        c[4] = g_gw[128]; c[5] = g_GC[0]; c[6] = g_GC[1];
    }
    __syncthreads();

    int t = blockIdx.x * 256 + threadIdx.x;
    if (t >= EB) return;
    int e = t >> 3;
    int b = t & 7;

    float xup = g_xv[t];
    float xdn = g_xv[EB + t];
    float al  = alpha[e];

    float xv = c[0] * xup + c[1] * xdn + c[2] * al + c[3];
    float v = (xv > 0.f) ? (xv + __logf(1.0f + __expf(-xv)))
                         : __logf(1.0f + __expf(xv));
    v = fminf(v, 3.0f);
    float Tt = __fdividef(dist[e], v + 1e-5f);

    float Tidx = fminf(fmaxf(rintf(Tt * 0.1f), 0.0f), 11.0f);
    int   n    = T_IN - (int)Tidx;                  // 1..12
    float alc  = fminf(fmaxf(al, 0.f), 1.f);
    float F    = __fdividef(1.0f, 1.0f + alc * Tt);
    float omF  = 1.0f - F;

    int se = src[e];
    int de = dst[e];

    float f[T_IN];
    {
        const float4* f4 = reinterpret_cast<const float4*>(feat)
                           + ((size_t)se * B + b) * 3;
        float4 q0 = f4[0], q1 = f4[1], q2 = f4[2];
        f[0]=q0.x; f[1]=q0.y; f[2]=q0.z;  f[3]=q0.w;
        f[4]=q1.x; f[5]=q1.y; f[6]=q1.z;  f[7]=q1.w;
        f[8]=q2.x; f[9]=q2.y; f[10]=q2.z; f[11]=q2.w;
    }
    float acc = 0.f, pw = 0.f;
#pragma unroll
    for (int k = T_IN - 1; k >= 0; --k) {
        if (k == n - 1) pw = F;
        if (k <= n - 1) { acc = fmaf(pw, f[k], acc); pw *= omF; }
    }

    float4 ns = g_node[se * B + b];
    float4 nd = g_node[de * B + b];
    float Ssum = ns.z + nd.z + Tt;
    float m    = Ssum * (1.0f / 129.0f);
    float q    = ns.w + nd.w + Tt * Tt;
    float var  = q * (1.0f / 129.0f) - m * m;
    float dot  = ns.x + nd.y + Tt * c[4];
    float a    = (dot - m * c[5]) * rsqrtf(var + 1e-5f) + c[6];
    a = (a >= 0.f) ? a : 0.01f * a;                 // leaky_relu

    // softmax without max-shift (exactly invariant): ex = exp(a)
    float ex = __expf(a);
    g_att[t]  = ex;
    g_dsum[t] = acc;
    atomicAdd(&g_den[se * B + b], ex);
}

// ---------------- edge pass 3: pred[dst] += ex/den[src] * dsum ----------------
__global__ __launch_bounds__(256)
void edge3_kernel(const int* __restrict__ src, const int* __restrict__ dst,
                  float* __restrict__ out) {
    int t = blockIdx.x * 256 + threadIdx.x;
    if (t >= EB) return;
    int e = t >> 3, b = t & 7;
    int se = src[e];
    int de = dst[e];
    float val = __fdividef(g_att[t], g_den[se * B + b]) * g_dsum[t];
    atomicAdd(&out[de * B + b], val);
}

// ---------------- launch ----------------
extern "C" void kernel_launch(void* const* d_in, const int* in_sizes, int n_in,
                              void* d_out, int out_size) {
    bool sig_order = (n_in >= 6 && in_sizes[5] == HP * T_IN);   // fc_w=768 at idx 5

    int i_src, i_dst, i_alpha, i_fcw, i_ln2g, i_ln2b, i_attnw;
    int i_l11w, i_l11b, i_ln11g, i_ln11b, i_l12w, i_l12b;
    int i_l21w, i_l21b, i_ln21g, i_ln21b, i_l22w, i_l22b, i_l3w, i_l3b;

    if (!sig_order) {
        i_src = 4;  i_dst = 5;  i_alpha = 6;  i_fcw = 7;
        i_ln2g = 8; i_ln2b = 9; i_attnw = 10;
        i_l11w = 11; i_l11b = 12; i_ln11g = 13; i_ln11b = 14; i_l12w = 15; i_l12b = 16;
        i_l21w = 17; i_l21b = 18; i_ln21g = 19; i_ln21b = 20; i_l22w = 21; i_l22b = 22;
        i_l3w = 23;  i_l3b = 24;
    } else {
        i_alpha = 4; i_fcw = 5;
        i_ln2g = 6;  i_ln2b = 7; i_attnw = 8;
        i_l11w = 9;  i_l11b = 10; i_ln11g = 11; i_ln11b = 12; i_l12w = 13; i_l12b = 14;
        i_l21w = 15; i_l21b = 16; i_ln21g = 17; i_ln21b = 18; i_l22w = 19; i_l22b = 20;
        i_l3w = 21;  i_l3b = 22;  i_src = 23;   i_dst = 24;
    }

    const float* feat  = (const float*)d_in[0];
    const float* up    = (const float*)d_in[1];
    const float* dn    = (const float*)d_in[2];
    const float* dist  = (const float*)d_in[3];
    const float* alpha = (const float*)d_in[i_alpha];
    const int*   src   = (const int*)d_in[i_src];
    const int*   dst   = (const int*)d_in[i_dst];
    float* out = (float*)d_out;

    float* xv_up;
    float* xv_dn;
    cudaGetSymbolAddress((void**)&xv_up, g_xv);
    xv_dn = xv_up + EB;

    prep_kernel<<<1, 256>>>((const float*)d_in[i_ln2g],
                            (const float*)d_in[i_ln2b],
                            (const float*)d_in[i_attnw]);

    init_kernel<<<(NB + 255) / 256, 256>>>(out);

    node_kernel<<<NB / 128, 128>>>(feat, (const float*)d_in[i_fcw]);

    vel_kernel<<<EB / 256, 256>>>(
        up,
        (const float*)d_in[i_l11w], (const float*)d_in[i_l11b],
        (const float*)d_in[i_ln11g], (const float*)d_in[i_ln11b],
        (const float*)d_in[i_l12w], (const float*)d_in[i_l12b],
        xv_up);
    vel_kernel<<<EB / 256, 256>>>(
        dn,
        (const float*)d_in[i_l21w], (const float*)d_in[i_l21b],
        (const float*)d_in[i_ln21g], (const float*)d_in[i_ln21b],
        (const float*)d_in[i_l22w], (const float*)d_in[i_l22b],
        xv_dn);

    edgeA_kernel<<<EB / 256, 256>>>(dist, alpha, feat, src, dst,
                                    (const float*)d_in[i_l3w],
                                    (const float*)d_in[i_l3b]);
    edge3_kernel<<<EB / 256, 256>>>(src, dst, out);
}

// round 8
// speedup vs baseline: 1.3168x; 1.3168x over previous
#include <cuda_runtime.h>
#include <math.h>

// ---------------- problem constants ----------------
constexpr int N_NODES = 10000;
constexpr int N_EDGES = 160000;
constexpr int B       = 8;
constexpr int T_IN    = 12;
constexpr int HP      = 64;
constexpr int HV      = 32;
constexpr int CDIM    = 2 * HP + 1;   // 129
constexpr int NB      = N_NODES * B;  // 80000
constexpr int EB      = N_EDGES * B;  // 1280000

// ---------------- device scratch (static; no allocation) ----------------
__device__ float4 g_node[NB];     // per (node,b): P, R, S, Q
__device__ float  g_att[EB];      // ex = exp(a)
__device__ float  g_dsum[EB];     // sum_k diff*feature[src]
__device__ float  g_den[NB];      // softmax denominator
__device__ float  g_gw[CDIM];     // ln2_g * attn_w
__device__ float  g_GC[2];        // [0]=sum(g*w), [1]=sum(b*w)
__device__ float  g_xv[2 * EB];   // [0..EB): x_up ; [EB..2EB): x_dn

// ---------------- packed f32x2 helpers: values live in u64 regs ----------------
using U64 = unsigned long long;

__device__ __forceinline__ U64 ffma2(U64 a, U64 b, U64 c) {
    U64 d;
    asm("fma.rn.f32x2 %0, %1, %2, %3;" : "=l"(d) : "l"(a), "l"(b), "l"(c));
    return d;
}
__device__ __forceinline__ U64 add2(U64 a, U64 b) {
    U64 d;
    asm("add.rn.f32x2 %0, %1, %2;" : "=l"(d) : "l"(a), "l"(b));
    return d;
}
__device__ __forceinline__ U64 mul2(U64 a, U64 b) {
    U64 d;
    asm("mul.rn.f32x2 %0, %1, %2;" : "=l"(d) : "l"(a), "l"(b));
    return d;
}
__device__ __forceinline__ U64 pack2(float lo, float hi) {
    U64 d;
    asm("mov.b64 %0, {%1, %2};" : "=l"(d) : "f"(lo), "f"(hi));
    return d;
}
__device__ __forceinline__ void unpack2(U64 v, float& lo, float& hi) {
    asm("mov.b64 {%0, %1}, %2;" : "=f"(lo), "=f"(hi) : "l"(v));
}

// ---------------- prep: gw = ln2_g*attn_w; G = sum(gw); C = sum(ln2_b*attn_w) --------
__global__ void prep_kernel(const float* __restrict__ ln2g,
                            const float* __restrict__ ln2b,
                            const float* __restrict__ attnw) {
    __shared__ float sG[256];
    __shared__ float sC[256];
    int t = threadIdx.x;
    float gv = 0.f, cv = 0.f;
    if (t < CDIM) {
        float w = attnw[t];
        gv = ln2g[t] * w;
        cv = ln2b[t] * w;
        g_gw[t] = gv;
    }
    sG[t] = gv; sC[t] = cv;
    __syncthreads();
    for (int s = 128; s > 0; s >>= 1) {
        if (t < s) { sG[t] += sG[t + s]; sC[t] += sC[t + s]; }
        __syncthreads();
    }
    if (t == 0) { g_GC[0] = sG[0]; g_GC[1] = sC[0]; }
}

// ---------------- init: zero pred, den ----------------
__global__ void init_kernel(float* __restrict__ out) {
    int t = blockIdx.x * blockDim.x + threadIdx.x;
    if (t < NB) {
        out[t]   = 0.f;
        g_den[t] = 0.f;
    }
}

// ---------------- node kernel: fold z into (P,R,S,Q) ----------------
__global__ __launch_bounds__(128)
void node_kernel(const float* __restrict__ feat,
                 const float* __restrict__ fcw) {
    __shared__ float sw[HP * T_IN];   // 768
    __shared__ float sgw[2 * HP];     // 128
    int tid = threadIdx.x;
    for (int i = tid; i < HP * T_IN; i += blockDim.x) sw[i]  = fcw[i];
    for (int i = tid; i < 2 * HP;    i += blockDim.x) sgw[i] = g_gw[i];
    __syncthreads();

    int t = blockIdx.x * blockDim.x + tid;
    if (t >= NB) return;

    float fr[T_IN];
    {
        const float4* f4 = reinterpret_cast<const float4*>(feat) + (size_t)t * 3;
        float4 a0 = f4[0], a1 = f4[1], a2 = f4[2];
        fr[0]=a0.x; fr[1]=a0.y; fr[2]=a0.z;  fr[3]=a0.w;
        fr[4]=a1.x; fr[5]=a1.y; fr[6]=a1.z;  fr[7]=a1.w;
        fr[8]=a2.x; fr[9]=a2.y; fr[10]=a2.z; fr[11]=a2.w;
    }

    float P = 0.f, R = 0.f, S = 0.f, Q = 0.f;
#pragma unroll
    for (int h = 0; h < HP; ++h) {
        float z = 0.f;
#pragma unroll
        for (int k = 0; k < T_IN; ++k) z = fmaf(sw[h * T_IN + k], fr[k], z);
        P = fmaf(z, sgw[h], P);
        R = fmaf(z, sgw[HP + h], R);
        S += z;
        Q = fmaf(z, z, Q);
    }
    g_node[t] = make_float4(P, R, S, Q);
}

// ---------------- velocity kernel: one thread = (edge, batch-pair), one branch ------
// sigmoid(w2 . relu(LN(W1 in + b1)) + b2) for 2 batch elems packed in f32x2 (u64 regs)
__global__ __launch_bounds__(256, 2)
void vel_kernel(const float* __restrict__ inp,
                const float* __restrict__ w1, const float* __restrict__ b1,
                const float* __restrict__ lg, const float* __restrict__ lb,
                const float* __restrict__ w2, const float* __restrict__ b2p,
                int out_base /* in float2 units */) {
    // duplicated weight pairs, 16B-aligned so LDS.128 yields ready u64 halves
    __shared__ __align__(16) float2 swp[HV * T_IN];   // (w,w) pairs, 3 KB
    __shared__ __align__(8)  float2 sb1u[HV], slgu[HV], slbu[HV];
    __shared__ float sw2s[HV];
    __shared__ float sb2;
    int tid = threadIdx.x;
    for (int i = tid; i < HV * T_IN; i += 256) { float w = w1[i]; swp[i] = make_float2(w, w); }
    if (tid < HV) {
        float b = b1[tid]; sb1u[tid] = make_float2(b, b);
        float g = lg[tid]; slgu[tid] = make_float2(g, g);
        float q = lb[tid]; slbu[tid] = make_float2(q, q);
        sw2s[tid] = w2[tid];
    }
    if (tid == 0) sb2 = b2p[0];
    __syncthreads();

    int t = blockIdx.x * 256 + tid;            // t < EB/2
    const float4* f4 = reinterpret_cast<const float4*>(inp) + (size_t)t * 6;
    float4 a0 = f4[0], a1 = f4[1], a2 = f4[2]; // batch elem 0 (12 floats)
    float4 a3 = f4[3], a4 = f4[4], a5 = f4[5]; // batch elem 1

    U64 in2[T_IN];
    in2[0]  = pack2(a0.x, a3.x); in2[1]  = pack2(a0.y, a3.y);
    in2[2]  = pack2(a0.z, a3.z); in2[3]  = pack2(a0.w, a3.w);
    in2[4]  = pack2(a1.x, a4.x); in2[5]  = pack2(a1.y, a4.y);
    in2[6]  = pack2(a1.z, a4.z); in2[7]  = pack2(a1.w, a4.w);
    in2[8]  = pack2(a2.x, a5.x); in2[9]  = pack2(a2.y, a5.y);
    in2[10] = pack2(a2.z, a5.z); in2[11] = pack2(a2.w, a5.w);

    const ulonglong2* sw2v = reinterpret_cast<const ulonglong2*>(swp);
    const U64* sb1v = reinterpret_cast<const U64*>(sb1u);
    const U64* slgv = reinterpret_cast<const U64*>(slgu);
    const U64* slbv = reinterpret_cast<const U64*>(slbu);

    U64 h[HV];
#pragma unroll
    for (int j = 0; j < HV; ++j) {
        U64 acc = sb1v[j];
#pragma unroll
        for (int kk = 0; kk < 6; ++kk) {
            ulonglong2 wp = sw2v[j * 6 + kk];     // (w_2k,w_2k) | (w_2k+1,w_2k+1)
            acc = ffma2(wp.x, in2[2 * kk],     acc);
            acc = ffma2(wp.y, in2[2 * kk + 1], acc);
        }
        h[j] = acc;
    }

    // LayerNorm across HV (per packed component)
    U64 s0 = add2(h[0], h[1]);
    U64 s1 = add2(h[2], h[3]);
#pragma unroll
    for (int j = 4; j < HV; j += 4) {
        s0 = add2(s0, add2(h[j],     h[j + 1]));
        s1 = add2(s1, add2(h[j + 2], h[j + 3]));
    }
    U64 sum = add2(s0, s1);
    U64 mean  = mul2(sum, pack2(1.0f / HV, 1.0f / HV));
    U64 nmean = mul2(mean, pack2(-1.0f, -1.0f));
    U64 var = pack2(0.f, 0.f);
#pragma unroll
    for (int j = 0; j < HV; ++j) {
        U64 d = add2(h[j], nmean);
        h[j] = d;                                   // keep centered value
        var = ffma2(d, d, var);
    }
    float v0, v1;
    unpack2(var, v0, v1);
    float i0 = rsqrtf(v0 * (1.0f / HV) + 1e-5f);
    float i1 = rsqrtf(v1 * (1.0f / HV) + 1e-5f);
    U64 inv = pack2(i0, i1);

    float acc0 = sb2, acc1 = sb2;
#pragma unroll
    for (int j = 0; j < HV; ++j) {
        U64 sc = mul2(inv, slgv[j]);
        U64 y  = ffma2(h[j], sc, slbv[j]);
        float y0, y1;
        unpack2(y, y0, y1);
        y0 = fmaxf(y0, 0.f); y1 = fmaxf(y1, 0.f);
        float w = sw2s[j];
        acc0 = fmaf(y0, w, acc0);
        acc1 = fmaf(y1, w, acc1);
    }
    float2 o;
    o.x = __fdividef(1.0f, 1.0f + __expf(-acc0));
    o.y = __fdividef(1.0f, 1.0f + __expf(-acc1));
    reinterpret_cast<float2*>(g_xv)[out_base + t] = o;
}

// ---------------- edge attention + diffusion (softmax numerator + den) -------------
__global__ __launch_bounds__(256)
void edgeA_kernel(const float* __restrict__ dist,
                  const float* __restrict__ alpha,
                  const float* __restrict__ feat,
                  const int* __restrict__ src,
                  const int* __restrict__ dst,
                  const float* __restrict__ l3w,
                  const float* __restrict__ l3b) {
    __shared__ float c[7];
    if (threadIdx.x == 0) {
        c[0] = l3w[0]; c[1] = l3w[1]; c[2] = l3w[2]; c[3] = l3b[0];
        c[4] = g_gw[128]; c[5] = g_GC[0]; c[6] = g_GC[1];
    }
    __syncthreads();

    int t = blockIdx.x * 256 + threadIdx.x;
    if (t >= EB) return;
    int e = t >> 3;
    int b = t & 7;

    float xup = g_xv[t];
    float xdn = g_xv[EB + t];
    float al  = alpha[e];

    float xv = c[0] * xup + c[1] * xdn + c[2] * al + c[3];
    float v = (xv > 0.f) ? (xv + __logf(1.0f + __expf(-xv)))
                         : __logf(1.0f + __expf(xv));
    v = fminf(v, 3.0f);
    float Tt = __fdividef(dist[e], v + 1e-5f);

    float Tidx = fminf(fmaxf(rintf(Tt * 0.1f), 0.0f), 11.0f);
    int   n    = T_IN - (int)Tidx;                  // 1..12
    float alc  = fminf(fmaxf(al, 0.f), 1.f);
    float F    = __fdividef(1.0f, 1.0f + alc * Tt);
    float omF  = 1.0f - F;

    int se = src[e];
    int de = dst[e];

    float f[T_IN];
    {
        const float4* f4 = reinterpret_cast<const float4*>(feat)
                           + ((size_t)se * B + b) * 3;
        float4 q0 = f4[0], q1 = f4[1], q2 = f4[2];
        f[0]=q0.x; f[1]=q0.y; f[2]=q0.z;  f[3]=q0.w;
        f[4]=q1.x; f[5]=q1.y; f[6]=q1.z;  f[7]=q1.w;
        f[8]=q2.x; f[9]=q2.y; f[10]=q2.z; f[11]=q2.w;
    }
    float acc = 0.f, pw = 0.f;
#pragma unroll
    for (int k = T_IN - 1; k >= 0; --k) {
        if (k == n - 1) pw = F;
        if (k <= n - 1) { acc = fmaf(pw, f[k], acc); pw *= omF; }
    }

    float4 ns = g_node[se * B + b];
    float4 nd = g_node[de * B + b];
    float Ssum = ns.z + nd.z + Tt;
    float m    = Ssum * (1.0f / 129.0f);
    float q    = ns.w + nd.w + Tt * Tt;
    float var  = q * (1.0f / 129.0f) - m * m;
    float dot  = ns.x + nd.y + Tt * c[4];
    float a    = (dot - m * c[5]) * rsqrtf(var + 1e-5f) + c[6];
    a = (a >= 0.f) ? a : 0.01f * a;                 // leaky_relu

    // softmax without max-shift (exactly invariant): ex = exp(a)
    float ex = __expf(a);
    g_att[t]  = ex;
    g_dsum[t] = acc;
    atomicAdd(&g_den[se * B + b], ex);
}

// ---------------- edge pass 3: pred[dst] += ex/den[src] * dsum ----------------
__global__ __launch_bounds__(256)
void edge3_kernel(const int* __restrict__ src, const int* __restrict__ dst,
                  float* __restrict__ out) {
    int t = blockIdx.x * 256 + threadIdx.x;
    if (t >= EB) return;
    int e = t >> 3, b = t & 7;
    int se = src[e];
    int de = dst[e];
    float val = __fdividef(g_att[t], g_den[se * B + b]) * g_dsum[t];
    atomicAdd(&out[de * B + b], val);
}

// ---------------- launch ----------------
extern "C" void kernel_launch(void* const* d_in, const int* in_sizes, int n_in,
                              void* d_out, int out_size) {
    bool sig_order = (n_in >= 6 && in_sizes[5] == HP * T_IN);   // fc_w=768 at idx 5

    int i_src, i_dst, i_alpha, i_fcw, i_ln2g, i_ln2b, i_attnw;
    int i_l11w, i_l11b, i_ln11g, i_ln11b, i_l12w, i_l12b;
    int i_l21w, i_l21b, i_ln21g, i_ln21b, i_l22w, i_l22b, i_l3w, i_l3b;

    if (!sig_order) {
        i_src = 4;  i_dst = 5;  i_alpha = 6;  i_fcw = 7;
        i_ln2g = 8; i_ln2b = 9; i_attnw = 10;
        i_l11w = 11; i_l11b = 12; i_ln11g = 13; i_ln11b = 14; i_l12w = 15; i_l12b = 16;
        i_l21w = 17; i_l21b = 18; i_ln21g = 19; i_ln21b = 20; i_l22w = 21; i_l22b = 22;
        i_l3w = 23;  i_l3b = 24;
    } else {
        i_alpha = 4; i_fcw = 5;
        i_ln2g = 6;  i_ln2b = 7; i_attnw = 8;
        i_l11w = 9;  i_l11b = 10; i_ln11g = 11; i_ln11b = 12; i_l12w = 13; i_l12b = 14;
        i_l21w = 15; i_l21b = 16; i_ln21g = 17; i_ln21b = 18; i_l22w = 19; i_l22b = 20;
        i_l3w = 21;  i_l3b = 22;  i_src = 23;   i_dst = 24;
    }

    const float* feat  = (const float*)d_in[0];
    const float* up    = (const float*)d_in[1];
    const float* dn    = (const float*)d_in[2];
    const float* dist  = (const float*)d_in[3];
    const float* alpha = (const float*)d_in[i_alpha];
    const int*   src   = (const int*)d_in[i_src];
    const int*   dst   = (const int*)d_in[i_dst];
    float* out = (float*)d_out;

    prep_kernel<<<1, 256>>>((const float*)d_in[i_ln2g],
                            (const float*)d_in[i_ln2b],
                            (const float*)d_in[i_attnw]);

    init_kernel<<<(NB + 255) / 256, 256>>>(out);

    node_kernel<<<NB / 128, 128>>>(feat, (const float*)d_in[i_fcw]);

    vel_kernel<<<(EB / 2) / 256, 256>>>(
        up,
        (const float*)d_in[i_l11w], (const float*)d_in[i_l11b],
        (const float*)d_in[i_ln11g], (const float*)d_in[i_ln11b],
        (const float*)d_in[i_l12w], (const float*)d_in[i_l12b],
        0);
    vel_kernel<<<(EB / 2) / 256, 256>>>(
        dn,
        (const float*)d_in[i_l21w], (const float*)d_in[i_l21b],
        (const float*)d_in[i_ln21g], (const float*)d_in[i_ln21b],
        (const float*)d_in[i_l22w], (const float*)d_in[i_l22b],
        EB / 2);

    edgeA_kernel<<<EB / 256, 256>>>(dist, alpha, feat, src, dst,
                                    (const float*)d_in[i_l3w],
                                    (const float*)d_in[i_l3b]);
    edge3_kernel<<<EB / 256, 256>>>(src, dst, out);
}

// round 9
// speedup vs baseline: 1.3329x; 1.0122x over previous
#include <cuda_runtime.h>
#include <math.h>

// ---------------- problem constants ----------------
constexpr int N_NODES = 10000;
constexpr int N_EDGES = 160000;
constexpr int B       = 8;
constexpr int T_IN    = 12;
constexpr int HP      = 64;
constexpr int HV      = 32;
constexpr int CDIM    = 2 * HP + 1;   // 129
constexpr int NB      = N_NODES * B;  // 80000
constexpr int EB      = N_EDGES * B;  // 1280000

// ---------------- device scratch (static; no allocation) ----------------
__device__ float4 g_node[NB];     // per (node,b): P, R, S, Q
__device__ float  g_att[EB];      // ex = exp(a)
__device__ float  g_dsum[EB];     // sum_k diff*feature[src]
__device__ float  g_den[NB];      // softmax denominator
__device__ float  g_gw[CDIM];     // ln2_g * attn_w
__device__ float  g_GC[2];        // [0]=sum(g*w), [1]=sum(b*w)
__device__ float  g_xv[2 * EB];   // [0..EB): x_up ; [EB..2EB): x_dn

// ---------------- packed f32x2 helpers: in-place accumulation, u64 regs -------------
using U64 = unsigned long long;

__device__ __forceinline__ void ffma2_acc(U64& c, U64 a, U64 b) {
    asm("fma.rn.f32x2 %0, %1, %2, %0;" : "+l"(c) : "l"(a), "l"(b));
}
__device__ __forceinline__ void add2_acc(U64& c, U64 a) {
    asm("add.rn.f32x2 %0, %0, %1;" : "+l"(c) : "l"(a));
}
__device__ __forceinline__ U64 mul2(U64 a, U64 b) {
    U64 d;
    asm("mul.rn.f32x2 %0, %1, %2;" : "=l"(d) : "l"(a), "l"(b));
    return d;
}
__device__ __forceinline__ U64 pack2(float lo, float hi) {
    U64 d;
    asm("mov.b64 %0, {%1, %2};" : "=l"(d) : "f"(lo), "f"(hi));
    return d;
}
__device__ __forceinline__ void unpack2(U64 v, float& lo, float& hi) {
    asm("mov.b64 {%0, %1}, %2;" : "=f"(lo), "=f"(hi) : "l"(v));
}

// ---------------- prep: gw = ln2_g*attn_w; G = sum(gw); C = sum(ln2_b*attn_w) --------
__global__ void prep_kernel(const float* __restrict__ ln2g,
                            const float* __restrict__ ln2b,
                            const float* __restrict__ attnw) {
    __shared__ float sG[256];
    __shared__ float sC[256];
    int t = threadIdx.x;
    float gv = 0.f, cv = 0.f;
    if (t < CDIM) {
        float w = attnw[t];
        gv = ln2g[t] * w;
        cv = ln2b[t] * w;
        g_gw[t] = gv;
    }
    sG[t] = gv; sC[t] = cv;
    __syncthreads();
    for (int s = 128; s > 0; s >>= 1) {
        if (t < s) { sG[t] += sG[t + s]; sC[t] += sC[t + s]; }
        __syncthreads();
    }
    if (t == 0) { g_GC[0] = sG[0]; g_GC[1] = sC[0]; }
}

// ---------------- init: zero pred, den ----------------
__global__ void init_kernel(float* __restrict__ out) {
    int t = blockIdx.x * blockDim.x + threadIdx.x;
    if (t < NB) {
        out[t]   = 0.f;
        g_den[t] = 0.f;
    }
}

// ---------------- node kernel: fold z into (P,R,S,Q) ----------------
__global__ __launch_bounds__(128)
void node_kernel(const float* __restrict__ feat,
                 const float* __restrict__ fcw) {
    __shared__ float sw[HP * T_IN];   // 768
    __shared__ float sgw[2 * HP];     // 128
    int tid = threadIdx.x;
    for (int i = tid; i < HP * T_IN; i += blockDim.x) sw[i]  = fcw[i];
    for (int i = tid; i < 2 * HP;    i += blockDim.x) sgw[i] = g_gw[i];
    __syncthreads();

    int t = blockIdx.x * blockDim.x + tid;
    if (t >= NB) return;

    float fr[T_IN];
    {
        const float4* f4 = reinterpret_cast<const float4*>(feat) + (size_t)t * 3;
        float4 a0 = f4[0], a1 = f4[1], a2 = f4[2];
        fr[0]=a0.x; fr[1]=a0.y; fr[2]=a0.z;  fr[3]=a0.w;
        fr[4]=a1.x; fr[5]=a1.y; fr[6]=a1.z;  fr[7]=a1.w;
        fr[8]=a2.x; fr[9]=a2.y; fr[10]=a2.z; fr[11]=a2.w;
    }

    float P = 0.f, R = 0.f, S = 0.f, Q = 0.f;
#pragma unroll
    for (int h = 0; h < HP; ++h) {
        float z = 0.f;
#pragma unroll
        for (int k = 0; k < T_IN; ++k) z = fmaf(sw[h * T_IN + k], fr[k], z);
        P = fmaf(z, sgw[h], P);
        R = fmaf(z, sgw[HP + h], R);
        S += z;
        Q = fmaf(z, z, Q);
    }
    g_node[t] = make_float4(P, R, S, Q);
}

// ---------------- velocity kernel: one thread = (edge, batch-pair), one branch ------
// sigmoid(w2 . relu(LN(W1 in + b1)) + b2) for 2 batch elems packed in f32x2 (u64 regs)
__global__ __launch_bounds__(256, 2)
void vel_kernel(const float* __restrict__ inp,
                const float* __restrict__ w1, const float* __restrict__ b1,
                const float* __restrict__ lg, const float* __restrict__ lb,
                const float* __restrict__ w2, const float* __restrict__ b2p,
                int out_base /* in float2 units */) {
    // duplicated weight pairs, 16B-aligned so LDS.128 yields ready u64 halves
    __shared__ __align__(16) float2 swp[HV * T_IN];   // (w,w) pairs, 3 KB
    __shared__ __align__(8)  float2 sb1u[HV], slgu[HV], slbu[HV];
    __shared__ float sw2s[HV];
    __shared__ float sb2;
    int tid = threadIdx.x;
    for (int i = tid; i < HV * T_IN; i += 256) { float w = w1[i]; swp[i] = make_float2(w, w); }
    if (tid < HV) {
        float b = b1[tid]; sb1u[tid] = make_float2(b, b);
        float g = lg[tid]; slgu[tid] = make_float2(g, g);
        float q = lb[tid]; slbu[tid] = make_float2(q, q);
        sw2s[tid] = w2[tid];
    }
    if (tid == 0) sb2 = b2p[0];
    __syncthreads();

    int t = blockIdx.x * 256 + tid;            // t < EB/2
    const float4* f4 = reinterpret_cast<const float4*>(inp) + (size_t)t * 6;
    float4 a0 = f4[0], a1 = f4[1], a2 = f4[2]; // batch elem 0 (12 floats)
    float4 a3 = f4[3], a4 = f4[4], a5 = f4[5]; // batch elem 1

    U64 in2[T_IN];
    in2[0]  = pack2(a0.x, a3.x); in2[1]  = pack2(a0.y, a3.y);
    in2[2]  = pack2(a0.z, a3.z); in2[3]  = pack2(a0.w, a3.w);
    in2[4]  = pack2(a1.x, a4.x); in2[5]  = pack2(a1.y, a4.y);
    in2[6]  = pack2(a1.z, a4.z); in2[7]  = pack2(a1.w, a4.w);
    in2[8]  = pack2(a2.x, a5.x); in2[9]  = pack2(a2.y, a5.y);
    in2[10] = pack2(a2.z, a5.z); in2[11] = pack2(a2.w, a5.w);

    const ulonglong2* sw2v = reinterpret_cast<const ulonglong2*>(swp);
    const U64* sb1v = reinterpret_cast<const U64*>(sb1u);
    const U64* slgv = reinterpret_cast<const U64*>(slgu);
    const U64* slbv = reinterpret_cast<const U64*>(slbu);

    // matvec + LN statistics fused; all accumulation in-place (no copy-back MOVs)
    U64 h[HV];
    U64 sum = pack2(0.f, 0.f);
    U64 qq  = pack2(0.f, 0.f);
#pragma unroll
    for (int j = 0; j < HV; ++j) {
        U64 acc = sb1v[j];
#pragma unroll
        for (int kk = 0; kk < 6; ++kk) {
            ulonglong2 wp = sw2v[j * 6 + kk];     // (w_2k,w_2k) | (w_2k+1,w_2k+1)
            ffma2_acc(acc, wp.x, in2[2 * kk]);
            ffma2_acc(acc, wp.y, in2[2 * kk + 1]);
        }
        h[j] = acc;
        add2_acc(sum, acc);
        ffma2_acc(qq, acc, acc);
    }

    float s0, s1, q0, q1;
    unpack2(sum, s0, s1);
    unpack2(qq,  q0, q1);
    float m0 = s0 * (1.0f / HV), m1 = s1 * (1.0f / HV);
    float i0 = rsqrtf(fmaf(-m0, m0, q0 * (1.0f / HV)) + 1e-5f);
    float i1 = rsqrtf(fmaf(-m1, m1, q1 * (1.0f / HV)) + 1e-5f);
    U64 nmean = pack2(-m0, -m1);
    U64 inv2  = pack2(i0, i1);

    float acc0 = sb2, acc1 = sb2;
#pragma unroll
    for (int j = 0; j < HV; ++j) {
        add2_acc(h[j], nmean);                 // center in place
        U64 sc = mul2(inv2, slgv[j]);
        U64 y  = slbv[j];
        ffma2_acc(y, h[j], sc);
        float y0, y1;
        unpack2(y, y0, y1);
        y0 = fmaxf(y0, 0.f); y1 = fmaxf(y1, 0.f);
        float w = sw2s[j];
        acc0 = fmaf(y0, w, acc0);
        acc1 = fmaf(y1, w, acc1);
    }
    float2 o;
    o.x = __fdividef(1.0f, 1.0f + __expf(-acc0));
    o.y = __fdividef(1.0f, 1.0f + __expf(-acc1));
    reinterpret_cast<float2*>(g_xv)[out_base + t] = o;
}

// ---------------- edge attention + diffusion (softmax numerator + den) -------------
__global__ __launch_bounds__(256)
void edgeA_kernel(const float* __restrict__ dist,
                  const float* __restrict__ alpha,
                  const float* __restrict__ feat,
                  const int* __restrict__ src,
                  const int* __restrict__ dst,
                  const float* __restrict__ l3w,
                  const float* __restrict__ l3b) {
    __shared__ float c[7];
    if (threadIdx.x == 0) {
        c[0] = l3w[0]; c[1] = l3w[1]; c[2] = l3w[2]; c[3] = l3b[0];
        c[4] = g_gw[128]; c[5] = g_GC[0]; c[6] = g_GC[1];
    }
    __syncthreads();

    int t = blockIdx.x * 256 + threadIdx.x;
    if (t >= EB) return;
    int e = t >> 3;
    int b = t & 7;

    float xup = g_xv[t];
    float xdn = g_xv[EB + t];
    float al  = alpha[e];

    float xv = c[0] * xup + c[1] * xdn + c[2] * al + c[3];
    float v = (xv > 0.f) ? (xv + __logf(1.0f + __expf(-xv)))
                         : __logf(1.0f + __expf(xv));
    v = fminf(v, 3.0f);
    float Tt = __fdividef(dist[e], v + 1e-5f);

    float Tidx = fminf(fmaxf(rintf(Tt * 0.1f), 0.0f), 11.0f);
    int   n    = T_IN - (int)Tidx;                  // 1..12
    float alc  = fminf(fmaxf(al, 0.f), 1.f);
    float F    = __fdividef(1.0f, 1.0f + alc * Tt);
    float omF  = 1.0f - F;

    int se = src[e];
    int de = dst[e];

    float f[T_IN];
    {
        const float4* f4 = reinterpret_cast<const float4*>(feat)
                           + ((size_t)se * B + b) * 3;
        float4 q0 = f4[0], q1 = f4[1], q2 = f4[2];
        f[0]=q0.x; f[1]=q0.y; f[2]=q0.z;  f[3]=q0.w;
        f[4]=q1.x; f[5]=q1.y; f[6]=q1.z;  f[7]=q1.w;
        f[8]=q2.x; f[9]=q2.y; f[10]=q2.z; f[11]=q2.w;
    }
    float acc = 0.f, pw = 0.f;
#pragma unroll
    for (int k = T_IN - 1; k >= 0; --k) {
        if (k == n - 1) pw = F;
        if (k <= n - 1) { acc = fmaf(pw, f[k], acc); pw *= omF; }
    }

    float4 ns = g_node[se * B + b];
    float4 nd = g_node[de * B + b];
    float Ssum = ns.z + nd.z + Tt;
    float m    = Ssum * (1.0f / 129.0f);
    float q    = ns.w + nd.w + Tt * Tt;
    float var  = q * (1.0f / 129.0f) - m * m;
    float dot  = ns.x + nd.y + Tt * c[4];
    float a    = (dot - m * c[5]) * rsqrtf(var + 1e-5f) + c[6];
    a = (a >= 0.f) ? a : 0.01f * a;                 // leaky_relu

    // softmax without max-shift (exactly invariant): ex = exp(a)
    float ex = __expf(a);
    g_att[t]  = ex;
    g_dsum[t] = acc;
    atomicAdd(&g_den[se * B + b], ex);
}

// ---------------- edge pass 3: pred[dst] += ex/den[src] * dsum ----------------
__global__ __launch_bounds__(256)
void edge3_kernel(const int* __restrict__ src, const int* __restrict__ dst,
                  float* __restrict__ out) {
    int t = blockIdx.x * 256 + threadIdx.x;
    if (t >= EB) return;
    int e = t >> 3, b = t & 7;
    int se = src[e];
    int de = dst[e];
    float val = __fdividef(g_att[t], g_den[se * B + b]) * g_dsum[t];
    atomicAdd(&out[de * B + b], val);
}

// ---------------- launch ----------------
extern "C" void kernel_launch(void* const* d_in, const int* in_sizes, int n_in,
                              void* d_out, int out_size) {
    bool sig_order = (n_in >= 6 && in_sizes[5] == HP * T_IN);   // fc_w=768 at idx 5

    int i_src, i_dst, i_alpha, i_fcw, i_ln2g, i_ln2b, i_attnw;
    int i_l11w, i_l11b, i_ln11g, i_ln11b, i_l12w, i_l12b;
    int i_l21w, i_l21b, i_ln21g, i_ln21b, i_l22w, i_l22b, i_l3w, i_l3b;

    if (!sig_order) {
        i_src = 4;  i_dst = 5;  i_alpha = 6;  i_fcw = 7;
        i_ln2g = 8; i_ln2b = 9; i_attnw = 10;
        i_l11w = 11; i_l11b = 12; i_ln11g = 13; i_ln11b = 14; i_l12w = 15; i_l12b = 16;
        i_l21w = 17; i_l21b = 18; i_ln21g = 19; i_ln21b = 20; i_l22w = 21; i_l22b = 22;
        i_l3w = 23;  i_l3b = 24;
    } else {
        i_alpha = 4; i_fcw = 5;
        i_ln2g = 6;  i_ln2b = 7; i_attnw = 8;
        i_l11w = 9;  i_l11b = 10; i_ln11g = 11; i_ln11b = 12; i_l12w = 13; i_l12b = 14;
        i_l21w = 15; i_l21b = 16; i_ln21g = 17; i_ln21b = 18; i_l22w = 19; i_l22b = 20;
        i_l3w = 21;  i_l3b = 22;  i_src = 23;   i_dst = 24;
    }

    const float* feat  = (const float*)d_in[0];
    const float* up    = (const float*)d_in[1];
    const float* dn    = (const float*)d_in[2];
    const float* dist  = (const float*)d_in[3];
    const float* alpha = (const float*)d_in[i_alpha];
    const int*   src   = (const int*)d_in[i_src];
    const int*   dst   = (const int*)d_in[i_dst];
    float* out = (float*)d_out;

    prep_kernel<<<1, 256>>>((const float*)d_in[i_ln2g],
                            (const float*)d_in[i_ln2b],
                            (const float*)d_in[i_attnw]);

    init_kernel<<<(NB + 255) / 256, 256>>>(out);

    node_kernel<<<NB / 128, 128>>>(feat, (const float*)d_in[i_fcw]);

    vel_kernel<<<(EB / 2) / 256, 256>>>(
        up,
        (const float*)d_in[i_l11w], (const float*)d_in[i_l11b],
        (const float*)d_in[i_ln11g], (const float*)d_in[i_ln11b],
        (const float*)d_in[i_l12w], (const float*)d_in[i_l12b],
        0);
    vel_kernel<<<(EB / 2) / 256, 256>>>(
        dn,
        (const float*)d_in[i_l21w], (const float*)d_in[i_l21b],
        (const float*)d_in[i_ln21g], (const float*)d_in[i_ln21b],
        (const float*)d_in[i_l22w], (const float*)d_in[i_l22b],
        EB / 2);

    edgeA_kernel<<<EB / 256, 256>>>(dist, alpha, feat, src, dst,
                                    (const float*)d_in[i_l3w],
                                    (const float*)d_in[i_l3b]);
    edge3_kernel<<<EB / 256, 256>>>(src, dst, out);
}

// round 10
// speedup vs baseline: 1.8030x; 1.3528x over previous
#include <cuda_runtime.h>
#include <math.h>

// ---------------- problem constants ----------------
constexpr int N_NODES = 10000;
constexpr int N_EDGES = 160000;
constexpr int B       = 8;
constexpr int T_IN    = 12;
constexpr int HP      = 64;
constexpr int HV      = 32;
constexpr int HVP     = HV / 2;       // 16 hidden-unit pairs
constexpr int CDIM    = 2 * HP + 1;   // 129
constexpr int NB      = N_NODES * B;  // 80000
constexpr int EB      = N_EDGES * B;  // 1280000

// ---------------- device scratch (static; no allocation) ----------------
__device__ float4 g_node[NB];     // per (node,b): P, R, S, Q
__device__ float  g_att[EB];      // ex = exp(a)
__device__ float  g_dsum[EB];     // sum_k diff*feature[src]
__device__ float  g_den[NB];      // softmax denominator
__device__ float  g_gw[CDIM];     // ln2_g * attn_w
__device__ float  g_GC[2];        // [0]=sum(g*w), [1]=sum(b*w)
__device__ float  g_xv[2 * EB];   // [0..EB): x_up ; [EB..2EB): x_dn

// ---------------- packed f32x2 helpers ----------------
using U64 = unsigned long long;

__device__ __forceinline__ void ffma2_acc(U64& c, U64 a, U64 b) {
    asm("fma.rn.f32x2 %0, %1, %2, %0;" : "+l"(c) : "l"(a), "l"(b));
}
__device__ __forceinline__ void add2_acc(U64& c, U64 a) {
    asm("add.rn.f32x2 %0, %0, %1;" : "+l"(c) : "l"(a));
}
__device__ __forceinline__ U64 mul2(U64 a, U64 b) {
    U64 d;
    asm("mul.rn.f32x2 %0, %1, %2;" : "=l"(d) : "l"(a), "l"(b));
    return d;
}
__device__ __forceinline__ U64 pack2(float lo, float hi) {
    U64 d;
    asm("mov.b64 %0, {%1, %2};" : "=l"(d) : "f"(lo), "f"(hi));
    return d;
}
__device__ __forceinline__ void unpack2(U64 v, float& lo, float& hi) {
    asm("mov.b64 {%0, %1}, %2;" : "=f"(lo), "=f"(hi) : "l"(v));
}

// ---------------- prep: gw = ln2_g*attn_w; G = sum(gw); C = sum(ln2_b*attn_w) --------
__global__ void prep_kernel(const float* __restrict__ ln2g,
                            const float* __restrict__ ln2b,
                            const float* __restrict__ attnw) {
    __shared__ float sG[256];
    __shared__ float sC[256];
    int t = threadIdx.x;
    float gv = 0.f, cv = 0.f;
    if (t < CDIM) {
        float w = attnw[t];
        gv = ln2g[t] * w;
        cv = ln2b[t] * w;
        g_gw[t] = gv;
    }
    sG[t] = gv; sC[t] = cv;
    __syncthreads();
    for (int s = 128; s > 0; s >>= 1) {
        if (t < s) { sG[t] += sG[t + s]; sC[t] += sC[t + s]; }
        __syncthreads();
    }
    if (t == 0) { g_GC[0] = sG[0]; g_GC[1] = sC[0]; }
}

// ---------------- init: zero pred, den ----------------
__global__ void init_kernel(float* __restrict__ out) {
    int t = blockIdx.x * blockDim.x + threadIdx.x;
    if (t < NB) {
        out[t]   = 0.f;
        g_den[t] = 0.f;
    }
}

// ---------------- node kernel: fold z into (P,R,S,Q) ----------------
__global__ __launch_bounds__(128)
void node_kernel(const float* __restrict__ feat,
                 const float* __restrict__ fcw) {
    __shared__ float sw[HP * T_IN];   // 768
    __shared__ float sgw[2 * HP];     // 128
    int tid = threadIdx.x;
    for (int i = tid; i < HP * T_IN; i += blockDim.x) sw[i]  = fcw[i];
    for (int i = tid; i < 2 * HP;    i += blockDim.x) sgw[i] = g_gw[i];
    __syncthreads();

    int t = blockIdx.x * blockDim.x + tid;
    if (t >= NB) return;

    float fr[T_IN];
    {
        const float4* f4 = reinterpret_cast<const float4*>(feat) + (size_t)t * 3;
        float4 a0 = f4[0], a1 = f4[1], a2 = f4[2];
        fr[0]=a0.x; fr[1]=a0.y; fr[2]=a0.z;  fr[3]=a0.w;
        fr[4]=a1.x; fr[5]=a1.y; fr[6]=a1.z;  fr[7]=a1.w;
        fr[8]=a2.x; fr[9]=a2.y; fr[10]=a2.z; fr[11]=a2.w;
    }

    float P = 0.f, R = 0.f, S = 0.f, Q = 0.f;
#pragma unroll
    for (int h = 0; h < HP; ++h) {
        float z = 0.f;
#pragma unroll
        for (int k = 0; k < T_IN; ++k) z = fmaf(sw[h * T_IN + k], fr[k], z);
        P = fmaf(z, sgw[h], P);
        R = fmaf(z, sgw[HP + h], R);
        S += z;
        Q = fmaf(z, z, Q);
    }
    g_node[t] = make_float4(P, R, S, Q);
}

// ---------------- velocity kernel: 1 thread = (edge, batch-pair), 1 branch ----------
// f32x2 packs TWO HIDDEN UNITS (not two batch elems) -> weights stored as natural
// pairs, NO duplication -> smem traffic halved (the measured bottleneck).
__global__ __launch_bounds__(256, 2)
void vel_kernel(const float* __restrict__ inp,
                const float* __restrict__ w1, const float* __restrict__ b1,
                const float* __restrict__ lg, const float* __restrict__ lb,
                const float* __restrict__ w2, const float* __restrict__ b2p,
                int out_base /* in float2 units */) {
    // swt[k][jp] = (w1[2jp][k], w1[2jp+1][k]); 12*16 pairs = 1.5 KB
    __shared__ __align__(16) float2 swt[T_IN * HVP];
    __shared__ __align__(8)  float2 sb1p[HVP], slgp[HVP], slbp[HVP], sw2p[HVP];
    __shared__ float sb2;
    int tid = threadIdx.x;
    if (tid < T_IN * HVP) {
        int k  = tid >> 4;           // 0..11
        int jp = tid & 15;           // 0..15
        swt[tid] = make_float2(w1[(2 * jp) * T_IN + k], w1[(2 * jp + 1) * T_IN + k]);
    }
    if (tid >= 192 && tid < 192 + HVP) {
        int jp = tid - 192;
        sb1p[jp] = make_float2(b1[2 * jp], b1[2 * jp + 1]);
        slgp[jp] = make_float2(lg[2 * jp], lg[2 * jp + 1]);
        slbp[jp] = make_float2(lb[2 * jp], lb[2 * jp + 1]);
        sw2p[jp] = make_float2(w2[2 * jp], w2[2 * jp + 1]);
    }
    if (tid == 240) sb2 = b2p[0];
    __syncthreads();

    int t = blockIdx.x * 256 + tid;            // t < EB/2
    const float4* f4 = reinterpret_cast<const float4*>(inp) + (size_t)t * 6;
    float4 a0 = f4[0], a1 = f4[1], a2 = f4[2]; // batch elem 0 (12 floats)
    float4 a3 = f4[3], a4 = f4[4], a5 = f4[5]; // batch elem 1

    float in0[T_IN] = {a0.x,a0.y,a0.z,a0.w, a1.x,a1.y,a1.z,a1.w, a2.x,a2.y,a2.z,a2.w};
    float in1[T_IN] = {a3.x,a3.y,a3.z,a3.w, a4.x,a4.y,a4.z,a4.w, a5.x,a5.y,a5.z,a5.w};

    const U64* sb1v = reinterpret_cast<const U64*>(sb1p);
    const ulonglong2* swt4 = reinterpret_cast<const ulonglong2*>(swt);

    // h pairs: h0[jp] = (h_{2jp}, h_{2jp+1}) for batch elem 0; h1 for elem 1
    U64 h0[HVP], h1[HVP];
#pragma unroll
    for (int jp = 0; jp < HVP; ++jp) { h0[jp] = sb1v[jp]; h1[jp] = sb1v[jp]; }

#pragma unroll
    for (int k = 0; k < T_IN; ++k) {
        U64 x0 = pack2(in0[k], in0[k]);
        U64 x1 = pack2(in1[k], in1[k]);
#pragma unroll
        for (int jj = 0; jj < HVP / 2; ++jj) {      // 8 x LDS.128 per k
            ulonglong2 wp = swt4[k * 8 + jj];       // pairs jp=2jj, 2jj+1
            ffma2_acc(h0[2 * jj],     wp.x, x0);
            ffma2_acc(h0[2 * jj + 1], wp.y, x0);
            ffma2_acc(h1[2 * jj],     wp.x, x1);
            ffma2_acc(h1[2 * jj + 1], wp.y, x1);
        }
    }

    // LN stats (horizontal across packed pairs)
    U64 s0 = pack2(0.f, 0.f), q0 = pack2(0.f, 0.f);
    U64 s1 = pack2(0.f, 0.f), q1 = pack2(0.f, 0.f);
#pragma unroll
    for (int jp = 0; jp < HVP; ++jp) {
        add2_acc(s0, h0[jp]); ffma2_acc(q0, h0[jp], h0[jp]);
        add2_acc(s1, h1[jp]); ffma2_acc(q1, h1[jp], h1[jp]);
    }
    float sa, sb, qa, qb;
    unpack2(s0, sa, sb); unpack2(q0, qa, qb);
    float m0 = (sa + sb) * (1.0f / HV);
    float i0 = rsqrtf(fmaf(-m0, m0, (qa + qb) * (1.0f / HV)) + 1e-5f);
    unpack2(s1, sa, sb); unpack2(q1, qa, qb);
    float m1 = (sa + sb) * (1.0f / HV);
    float i1 = rsqrtf(fmaf(-m1, m1, (qa + qb) * (1.0f / HV)) + 1e-5f);

    U64 nm0 = pack2(-m0, -m0), iv0 = pack2(i0, i0);
    U64 nm1 = pack2(-m1, -m1), iv1 = pack2(i1, i1);

    const U64* slgv = reinterpret_cast<const U64*>(slgp);
    const U64* slbv = reinterpret_cast<const U64*>(slbp);

    float acc0 = sb2, acc1 = sb2;
#pragma unroll
    for (int jp = 0; jp < HVP; ++jp) {
        U64 gpair = slgv[jp];
        U64 bpair = slbv[jp];
        float2 wp2 = sw2p[jp];

        add2_acc(h0[jp], nm0);
        U64 sc0 = mul2(iv0, gpair);
        U64 y0p = bpair; ffma2_acc(y0p, h0[jp], sc0);
        float ya, yb;
        unpack2(y0p, ya, yb);
        ya = fmaxf(ya, 0.f); yb = fmaxf(yb, 0.f);
        acc0 = fmaf(ya, wp2.x, acc0); acc0 = fmaf(yb, wp2.y, acc0);

        add2_acc(h1[jp], nm1);
        U64 sc1 = mul2(iv1, gpair);
        U64 y1p = bpair; ffma2_acc(y1p, h1[jp], sc1);
        unpack2(y1p, ya, yb);
        ya = fmaxf(ya, 0.f); yb = fmaxf(yb, 0.f);
        acc1 = fmaf(ya, wp2.x, acc1); acc1 = fmaf(yb, wp2.y, acc1);
    }

    float2 o;
    o.x = __fdividef(1.0f, 1.0f + __expf(-acc0));
    o.y = __fdividef(1.0f, 1.0f + __expf(-acc1));
    reinterpret_cast<float2*>(g_xv)[out_base + t] = o;
}

// ---------------- edge attention + diffusion (softmax numerator + den) -------------
__global__ __launch_bounds__(256)
void edgeA_kernel(const float* __restrict__ dist,
                  const float* __restrict__ alpha,
                  const float* __restrict__ feat,
                  const int* __restrict__ src,
                  const int* __restrict__ dst,
                  const float* __restrict__ l3w,
                  const float* __restrict__ l3b) {
    __shared__ float c[7];
    if (threadIdx.x == 0) {
        c[0] = l3w[0]; c[1] = l3w[1]; c[2] = l3w[2]; c[3] = l3b[0];
        c[4] = g_gw[128]; c[5] = g_GC[0]; c[6] = g_GC[1];
    }
    __syncthreads();

    int t = blockIdx.x * 256 + threadIdx.x;
    if (t >= EB) return;
    int e = t >> 3;
    int b = t & 7;

    float xup = g_xv[t];
    float xdn = g_xv[EB + t];
    float al  = alpha[e];

    float xv = c[0] * xup + c[1] * xdn + c[2] * al + c[3];
    float v = (xv > 0.f) ? (xv + __logf(1.0f + __expf(-xv)))
                         : __logf(1.0f + __expf(xv));
    v = fminf(v, 3.0f);
    float Tt = __fdividef(dist[e], v + 1e-5f);

    float Tidx = fminf(fmaxf(rintf(Tt * 0.1f), 0.0f), 11.0f);
    int   n    = T_IN - (int)Tidx;                  // 1..12
    float alc  = fminf(fmaxf(al, 0.f), 1.f);
    float F    = __fdividef(1.0f, 1.0f + alc * Tt);
    float omF  = 1.0f - F;

    int se = src[e];
    int de = dst[e];

    float f[T_IN];
    {
        const float4* f4 = reinterpret_cast<const float4*>(feat)
                           + ((size_t)se * B + b) * 3;
        float4 q0 = f4[0], q1 = f4[1], q2 = f4[2];
        f[0]=q0.x; f[1]=q0.y; f[2]=q0.z;  f[3]=q0.w;
        f[4]=q1.x; f[5]=q1.y; f[6]=q1.z;  f[7]=q1.w;
        f[8]=q2.x; f[9]=q2.y; f[10]=q2.z; f[11]=q2.w;
    }
    float acc = 0.f, pw = 0.f;
#pragma unroll
    for (int k = T_IN - 1; k >= 0; --k) {
        if (k == n - 1) pw = F;
        if (k <= n - 1) { acc = fmaf(pw, f[k], acc); pw *= omF; }
    }

    float4 ns = g_node[se * B + b];
    float4 nd = g_node[de * B + b];
    float Ssum = ns.z + nd.z + Tt;
    float m    = Ssum * (1.0f / 129.0f);
    float q    = ns.w + nd.w + Tt * Tt;
    float var  = q * (1.0f / 129.0f) - m * m;
    float dot  = ns.x + nd.y + Tt * c[4];
    float a    = (dot - m * c[5]) * rsqrtf(var + 1e-5f) + c[6];
    a = (a >= 0.f) ? a : 0.01f * a;                 // leaky_relu

    // softmax without max-shift (exactly invariant): ex = exp(a)
    float ex = __expf(a);
    g_att[t]  = ex;
    g_dsum[t] = acc;
    atomicAdd(&g_den[se * B + b], ex);
}

// ---------------- edge pass 3: pred[dst] += ex/den[src] * dsum ----------------
__global__ __launch_bounds__(256)
void edge3_kernel(const int* __restrict__ src, const int* __restrict__ dst,
                  float* __restrict__ out) {
    int t = blockIdx.x * 256 + threadIdx.x;
    if (t >= EB) return;
    int e = t >> 3, b = t & 7;
    int se = src[e];
    int de = dst[e];
    float val = __fdividef(g_att[t], g_den[se * B + b]) * g_dsum[t];
    atomicAdd(&out[de * B + b], val);
}

// ---------------- launch ----------------
extern "C" void kernel_launch(void* const* d_in, const int* in_sizes, int n_in,
                              void* d_out, int out_size) {
    bool sig_order = (n_in >= 6 && in_sizes[5] == HP * T_IN);   // fc_w=768 at idx 5

    int i_src, i_dst, i_alpha, i_fcw, i_ln2g, i_ln2b, i_attnw;
    int i_l11w, i_l11b, i_ln11g, i_ln11b, i_l12w, i_l12b;
    int i_l21w, i_l21b, i_ln21g, i_ln21b, i_l22w, i_l22b, i_l3w, i_l3b;

    if (!sig_order) {
        i_src = 4;  i_dst = 5;  i_alpha = 6;  i_fcw = 7;
        i_ln2g = 8; i_ln2b = 9; i_attnw = 10;
        i_l11w = 11; i_l11b = 12; i_ln11g = 13; i_ln11b = 14; i_l12w = 15; i_l12b = 16;
        i_l21w = 17; i_l21b = 18; i_ln21g = 19; i_ln21b = 20; i_l22w = 21; i_l22b = 22;
        i_l3w = 23;  i_l3b = 24;
    } else {
        i_alpha = 4; i_fcw = 5;
        i_ln2g = 6;  i_ln2b = 7; i_attnw = 8;
        i_l11w = 9;  i_l11b = 10; i_ln11g = 11; i_ln11b = 12; i_l12w = 13; i_l12b = 14;
        i_l21w = 15; i_l21b = 16; i_ln21g = 17; i_ln21b = 18; i_l22w = 19; i_l22b = 20;
        i_l3w = 21;  i_l3b = 22;  i_src = 23;   i_dst = 24;
    }

    const float* feat  = (const float*)d_in[0];
    const float* up    = (const float*)d_in[1];
    const float* dn    = (const float*)d_in[2];
    const float* dist  = (const float*)d_in[3];
    const float* alpha = (const float*)d_in[i_alpha];
    const int*   src   = (const int*)d_in[i_src];
    const int*   dst   = (const int*)d_in[i_dst];
    float* out = (float*)d_out;

    prep_kernel<<<1, 256>>>((const float*)d_in[i_ln2g],
                            (const float*)d_in[i_ln2b],
                            (const float*)d_in[i_attnw]);

    init_kernel<<<(NB + 255) / 256, 256>>>(out);

    node_kernel<<<NB / 128, 128>>>(feat, (const float*)d_in[i_fcw]);

    vel_kernel<<<(EB / 2) / 256, 256>>>(
        up,
        (const float*)d_in[i_l11w], (const float*)d_in[i_l11b],
        (const float*)d_in[i_ln11g], (const float*)d_in[i_ln11b],
        (const float*)d_in[i_l12w], (const float*)d_in[i_l12b],
        0);
    vel_kernel<<<(EB / 2) / 256, 256>>>(
        dn,
        (const float*)d_in[i_l21w], (const float*)d_in[i_l21b],
        (const float*)d_in[i_ln21g], (const float*)d_in[i_ln21b],
        (const float*)d_in[i_l22w], (const float*)d_in[i_l22b],
        EB / 2);

    edgeA_kernel<<<EB / 256, 256>>>(dist, alpha, feat, src, dst,
                                    (const float*)d_in[i_l3w],
                                    (const float*)d_in[i_l3b]);
    edge3_kernel<<<EB / 256, 256>>>(src, dst, out);
}

// round 11
// speedup vs baseline: 1.8424x; 1.0218x over previous
#include <cuda_runtime.h>
#include <math.h>

// ---------------- problem constants ----------------
constexpr int N_NODES = 10000;
constexpr int N_EDGES = 160000;
constexpr int B       = 8;
constexpr int T_IN    = 12;
constexpr int HP      = 64;
constexpr int HV      = 32;
constexpr int HVP     = HV / 2;       // 16 hidden-unit pairs
constexpr int CDIM    = 2 * HP + 1;   // 129
constexpr int NB      = N_NODES * B;  // 80000
constexpr int EB      = N_EDGES * B;  // 1280000

// ---------------- device scratch (static; no allocation) ----------------
__device__ float4 g_node[NB];     // per (node,b): P, R, S, Q
__device__ float  g_att[EB];      // ex = exp(a)
__device__ float  g_dsum[EB];     // sum_k diff*feature[src]
__device__ float  g_den[NB];      // softmax denominator
__device__ float  g_gw[CDIM];     // ln2_g * attn_w
__device__ float  g_GC[2];        // [0]=sum(g*w), [1]=sum(b*w)

// ---------------- packed f32x2 helpers ----------------
using U64 = unsigned long long;

__device__ __forceinline__ void ffma2_acc(U64& c, U64 a, U64 b) {
    asm("fma.rn.f32x2 %0, %1, %2, %0;" : "+l"(c) : "l"(a), "l"(b));
}
__device__ __forceinline__ void add2_acc(U64& c, U64 a) {
    asm("add.rn.f32x2 %0, %0, %1;" : "+l"(c) : "l"(a));
}
__device__ __forceinline__ U64 mul2(U64 a, U64 b) {
    U64 d;
    asm("mul.rn.f32x2 %0, %1, %2;" : "=l"(d) : "l"(a), "l"(b));
    return d;
}
__device__ __forceinline__ U64 pack2(float lo, float hi) {
    U64 d;
    asm("mov.b64 %0, {%1, %2};" : "=l"(d) : "f"(lo), "f"(hi));
    return d;
}
__device__ __forceinline__ void unpack2(U64 v, float& lo, float& hi) {
    asm("mov.b64 {%0, %1}, %2;" : "=f"(lo), "=f"(hi) : "l"(v));
}

// ---------------- prep: gw = ln2_g*attn_w; G = sum(gw); C = sum(ln2_b*attn_w) --------
__global__ void prep_kernel(const float* __restrict__ ln2g,
                            const float* __restrict__ ln2b,
                            const float* __restrict__ attnw) {
    __shared__ float sG[256];
    __shared__ float sC[256];
    int t = threadIdx.x;
    float gv = 0.f, cv = 0.f;
    if (t < CDIM) {
        float w = attnw[t];
        gv = ln2g[t] * w;
        cv = ln2b[t] * w;
        g_gw[t] = gv;
    }
    sG[t] = gv; sC[t] = cv;
    __syncthreads();
    for (int s = 128; s > 0; s >>= 1) {
        if (t < s) { sG[t] += sG[t + s]; sC[t] += sC[t + s]; }
        __syncthreads();
    }
    if (t == 0) { g_GC[0] = sG[0]; g_GC[1] = sC[0]; }
}

// ---------------- init: zero pred, den ----------------
__global__ void init_kernel(float* __restrict__ out) {
    int t = blockIdx.x * blockDim.x + threadIdx.x;
    if (t < NB) {
        out[t]   = 0.f;
        g_den[t] = 0.f;
    }
}

// ---------------- node kernel: fold z into (P,R,S,Q) ----------------
__global__ __launch_bounds__(128)
void node_kernel(const float* __restrict__ feat,
                 const float* __restrict__ fcw) {
    __shared__ float sw[HP * T_IN];   // 768
    __shared__ float sgw[2 * HP];     // 128
    int tid = threadIdx.x;
    for (int i = tid; i < HP * T_IN; i += blockDim.x) sw[i]  = fcw[i];
    for (int i = tid; i < 2 * HP;    i += blockDim.x) sgw[i] = g_gw[i];
    __syncthreads();

    int t = blockIdx.x * blockDim.x + tid;
    if (t >= NB) return;

    float fr[T_IN];
    {
        const float4* f4 = reinterpret_cast<const float4*>(feat) + (size_t)t * 3;
        float4 a0 = f4[0], a1 = f4[1], a2 = f4[2];
        fr[0]=a0.x; fr[1]=a0.y; fr[2]=a0.z;  fr[3]=a0.w;
        fr[4]=a1.x; fr[5]=a1.y; fr[6]=a1.z;  fr[7]=a1.w;
        fr[8]=a2.x; fr[9]=a2.y; fr[10]=a2.z; fr[11]=a2.w;
    }

    float P = 0.f, R = 0.f, S = 0.f, Q = 0.f;
#pragma unroll
    for (int h = 0; h < HP; ++h) {
        float z = 0.f;
#pragma unroll
        for (int k = 0; k < T_IN; ++k) z = fmaf(sw[h * T_IN + k], fr[k], z);
        P = fmaf(z, sgw[h], P);
        R = fmaf(z, sgw[HP + h], R);
        S += z;
        Q = fmaf(z, z, Q);
    }
    g_node[t] = make_float4(P, R, S, Q);
}

// ---------------- velocity branch for 2 items (hidden-pair packed) ----------------
__device__ __forceinline__ float2 vbranch2(
    const ulonglong2* __restrict__ swt4,   // 8 x ulonglong2 per k
    const U64* __restrict__ sb1v,
    const U64* __restrict__ slgv,
    const U64* __restrict__ slbv,
    const float2* __restrict__ sw2p,
    float b2,
    const float* __restrict__ inp, size_t t /* item-pair index */) {

    const float4* f4 = reinterpret_cast<const float4*>(inp) + t * 6;
    float4 a0 = f4[0], a1 = f4[1], a2 = f4[2];
    float4 a3 = f4[3], a4 = f4[4], a5 = f4[5];

    float in0[T_IN] = {a0.x,a0.y,a0.z,a0.w, a1.x,a1.y,a1.z,a1.w, a2.x,a2.y,a2.z,a2.w};
    float in1[T_IN] = {a3.x,a3.y,a3.z,a3.w, a4.x,a4.y,a4.z,a4.w, a5.x,a5.y,a5.z,a5.w};

    U64 h0[HVP], h1[HVP];
#pragma unroll
    for (int jp = 0; jp < HVP; ++jp) { h0[jp] = sb1v[jp]; h1[jp] = sb1v[jp]; }

#pragma unroll
    for (int k = 0; k < T_IN; ++k) {
        U64 x0 = pack2(in0[k], in0[k]);
        U64 x1 = pack2(in1[k], in1[k]);
#pragma unroll
        for (int jj = 0; jj < HVP / 2; ++jj) {
            ulonglong2 wp = swt4[k * 8 + jj];
            ffma2_acc(h0[2 * jj],     wp.x, x0);
            ffma2_acc(h0[2 * jj + 1], wp.y, x0);
            ffma2_acc(h1[2 * jj],     wp.x, x1);
            ffma2_acc(h1[2 * jj + 1], wp.y, x1);
        }
    }

    U64 s0 = pack2(0.f, 0.f), q0 = pack2(0.f, 0.f);
    U64 s1 = pack2(0.f, 0.f), q1 = pack2(0.f, 0.f);
#pragma unroll
    for (int jp = 0; jp < HVP; ++jp) {
        add2_acc(s0, h0[jp]); ffma2_acc(q0, h0[jp], h0[jp]);
        add2_acc(s1, h1[jp]); ffma2_acc(q1, h1[jp], h1[jp]);
    }
    float sa, sb, qa, qb;
    unpack2(s0, sa, sb); unpack2(q0, qa, qb);
    float m0 = (sa + sb) * (1.0f / HV);
    float i0 = rsqrtf(fmaf(-m0, m0, (qa + qb) * (1.0f / HV)) + 1e-5f);
    unpack2(s1, sa, sb); unpack2(q1, qa, qb);
    float m1 = (sa + sb) * (1.0f / HV);
    float i1 = rsqrtf(fmaf(-m1, m1, (qa + qb) * (1.0f / HV)) + 1e-5f);

    U64 nm0 = pack2(-m0, -m0), iv0 = pack2(i0, i0);
    U64 nm1 = pack2(-m1, -m1), iv1 = pack2(i1, i1);

    float acc0 = b2, acc1 = b2;
#pragma unroll
    for (int jp = 0; jp < HVP; ++jp) {
        U64 gpair = slgv[jp];
        U64 bpair = slbv[jp];
        float2 wp2 = sw2p[jp];
        float ya, yb;

        add2_acc(h0[jp], nm0);
        U64 sc0 = mul2(iv0, gpair);
        U64 y0p = bpair; ffma2_acc(y0p, h0[jp], sc0);
        unpack2(y0p, ya, yb);
        ya = fmaxf(ya, 0.f); yb = fmaxf(yb, 0.f);
        acc0 = fmaf(ya, wp2.x, acc0); acc0 = fmaf(yb, wp2.y, acc0);

        add2_acc(h1[jp], nm1);
        U64 sc1 = mul2(iv1, gpair);
        U64 y1p = bpair; ffma2_acc(y1p, h1[jp], sc1);
        unpack2(y1p, ya, yb);
        ya = fmaxf(ya, 0.f); yb = fmaxf(yb, 0.f);
        acc1 = fmaf(ya, wp2.x, acc1); acc1 = fmaf(yb, wp2.y, acc1);
    }

    float2 o;
    o.x = __fdividef(1.0f, 1.0f + __expf(-acc0));
    o.y = __fdividef(1.0f, 1.0f + __expf(-acc1));
    return o;
}

// ---------------- fused kernel: vel-up + vel-dn + edge attention/diffusion ----------
struct FP {
    const float *up, *dn, *dist, *alpha, *feat;
    const int   *src, *dst;
    const float *w1u, *b1u, *lgu, *lbu, *w2u, *b2u;
    const float *w1d, *b1d, *lgd, *lbd, *w2d, *b2d;
    const float *l3w, *l3b;
};

__global__ __launch_bounds__(256, 2)
void fused_kernel(FP p) {
    __shared__ __align__(16) float2 sWU[T_IN * HVP];   // 1.5 KB
    __shared__ __align__(16) float2 sWD[T_IN * HVP];   // 1.5 KB
    __shared__ __align__(8)  float2 sb1U[HVP], slgU[HVP], slbU[HVP], sw2U[HVP];
    __shared__ __align__(8)  float2 sb1D[HVP], slgD[HVP], slbD[HVP], sw2D[HVP];
    __shared__ float sb2s[2];
    __shared__ float c[7];

    int tid = threadIdx.x;
    if (tid < T_IN * HVP) {
        int k  = tid >> 4;
        int jp = tid & 15;
        sWU[tid] = make_float2(p.w1u[(2*jp)*T_IN + k], p.w1u[(2*jp+1)*T_IN + k]);
        sWD[tid] = make_float2(p.w1d[(2*jp)*T_IN + k], p.w1d[(2*jp+1)*T_IN + k]);
    } else if (tid < 208) {
        int jp = tid - 192;
        sb1U[jp] = make_float2(p.b1u[2*jp], p.b1u[2*jp+1]);
        slgU[jp] = make_float2(p.lgu[2*jp], p.lgu[2*jp+1]);
        slbU[jp] = make_float2(p.lbu[2*jp], p.lbu[2*jp+1]);
        sw2U[jp] = make_float2(p.w2u[2*jp], p.w2u[2*jp+1]);
    } else if (tid < 224) {
        int jp = tid - 208;
        sb1D[jp] = make_float2(p.b1d[2*jp], p.b1d[2*jp+1]);
        slgD[jp] = make_float2(p.lgd[2*jp], p.lgd[2*jp+1]);
        slbD[jp] = make_float2(p.lbd[2*jp], p.lbd[2*jp+1]);
        sw2D[jp] = make_float2(p.w2d[2*jp], p.w2d[2*jp+1]);
    } else if (tid == 224) {
        sb2s[0] = p.b2u[0]; sb2s[1] = p.b2d[0];
        c[0] = p.l3w[0]; c[1] = p.l3w[1]; c[2] = p.l3w[2]; c[3] = p.l3b[0];
        c[4] = g_gw[128]; c[5] = g_GC[0]; c[6] = g_GC[1];
    }
    __syncthreads();

    size_t t = (size_t)blockIdx.x * 256 + tid;       // item-pair index, t < EB/2
    int e  = (int)(t >> 2);                          // 4 pairs per edge
    int b0 = ((int)t & 3) * 2;                       // even batch index

    // phase 1: upstream branch
    float2 xu = vbranch2(reinterpret_cast<const ulonglong2*>(sWU),
                         reinterpret_cast<const U64*>(sb1U),
                         reinterpret_cast<const U64*>(slgU),
                         reinterpret_cast<const U64*>(slbU),
                         sw2U, sb2s[0], p.up, t);
    // phase 2: downstream branch
    float2 xd = vbranch2(reinterpret_cast<const ulonglong2*>(sWD),
                         reinterpret_cast<const U64*>(sb1D),
                         reinterpret_cast<const U64*>(slgD),
                         reinterpret_cast<const U64*>(slbD),
                         sw2D, sb2s[1], p.dn, t);

    // phase 3: attention + diffusion for both items (same edge)
    float al   = p.alpha[e];
    float dste = p.dist[e];
    float alc  = fminf(fmaxf(al, 0.f), 1.f);
    int se = p.src[e];
    int de = p.dst[e];

    // gather feature rows (2 adjacent rows, 96 B contiguous)
    float f0[T_IN], f1[T_IN];
    {
        const float4* f4 = reinterpret_cast<const float4*>(p.feat)
                           + ((size_t)se * B + b0) * 3;
        float4 q0 = f4[0], q1 = f4[1], q2 = f4[2];
        float4 q3 = f4[3], q4 = f4[4], q5 = f4[5];
        f0[0]=q0.x; f0[1]=q0.y; f0[2]=q0.z;  f0[3]=q0.w;
        f0[4]=q1.x; f0[5]=q1.y; f0[6]=q1.z;  f0[7]=q1.w;
        f0[8]=q2.x; f0[9]=q2.y; f0[10]=q2.z; f0[11]=q2.w;
        f1[0]=q3.x; f1[1]=q3.y; f1[2]=q3.z;  f1[3]=q3.w;
        f1[4]=q4.x; f1[5]=q4.y; f1[6]=q4.z;  f1[7]=q4.w;
        f1[8]=q5.x; f1[9]=q5.y; f1[10]=q5.z; f1[11]=q5.w;
    }
    const float4* nsrc = &g_node[se * B + b0];
    const float4* ndst = &g_node[de * B + b0];

    float2 exo, dso;
#pragma unroll
    for (int i = 0; i < 2; ++i) {
        float xup = (i == 0) ? xu.x : xu.y;
        float xdn = (i == 0) ? xd.x : xd.y;
        const float* f = (i == 0) ? f0 : f1;

        float xv = c[0] * xup + c[1] * xdn + c[2] * al + c[3];
        float v = (xv > 0.f) ? (xv + __logf(1.0f + __expf(-xv)))
                             : __logf(1.0f + __expf(xv));
        v = fminf(v, 3.0f);
        float Tt = __fdividef(dste, v + 1e-5f);

        float Tidx = fminf(fmaxf(rintf(Tt * 0.1f), 0.0f), 11.0f);
        int   n    = T_IN - (int)Tidx;              // 1..12
        float F    = __fdividef(1.0f, 1.0f + alc * Tt);
        float omF  = 1.0f - F;

        float acc = 0.f, pw = 0.f;
#pragma unroll
        for (int k = T_IN - 1; k >= 0; --k) {
            if (k == n - 1) pw = F;
            if (k <= n - 1) { acc = fmaf(pw, f[k], acc); pw *= omF; }
        }

        float4 ns = nsrc[i];
        float4 nd = ndst[i];
        float Ssum = ns.z + nd.z + Tt;
        float m    = Ssum * (1.0f / 129.0f);
        float q    = ns.w + nd.w + Tt * Tt;
        float var  = q * (1.0f / 129.0f) - m * m;
        float dot  = ns.x + nd.y + Tt * c[4];
        float a    = (dot - m * c[5]) * rsqrtf(var + 1e-5f) + c[6];
        a = (a >= 0.f) ? a : 0.01f * a;             // leaky_relu

        float ex = __expf(a);
        if (i == 0) { exo.x = ex; dso.x = acc; }
        else        { exo.y = ex; dso.y = acc; }
        atomicAdd(&g_den[se * B + b0 + i], ex);
    }

    reinterpret_cast<float2*>(g_att)[t]  = exo;
    reinterpret_cast<float2*>(g_dsum)[t] = dso;
}

// ---------------- edge pass 3: pred[dst] += ex/den[src] * dsum ----------------
__global__ __launch_bounds__(256)
void edge3_kernel(const int* __restrict__ src, const int* __restrict__ dst,
                  float* __restrict__ out) {
    int t = blockIdx.x * 256 + threadIdx.x;
    if (t >= EB) return;
    int e = t >> 3, b = t & 7;
    int se = src[e];
    int de = dst[e];
    float val = __fdividef(g_att[t], g_den[se * B + b]) * g_dsum[t];
    atomicAdd(&out[de * B + b], val);
}

// ---------------- launch ----------------
extern "C" void kernel_launch(void* const* d_in, const int* in_sizes, int n_in,
                              void* d_out, int out_size) {
    bool sig_order = (n_in >= 6 && in_sizes[5] == HP * T_IN);   // fc_w=768 at idx 5

    int i_src, i_dst, i_alpha, i_fcw, i_ln2g, i_ln2b, i_attnw;
    int i_l11w, i_l11b, i_ln11g, i_ln11b, i_l12w, i_l12b;
    int i_l21w, i_l21b, i_ln21g, i_ln21b, i_l22w, i_l22b, i_l3w, i_l3b;

    if (!sig_order) {
        i_src = 4;  i_dst = 5;  i_alpha = 6;  i_fcw = 7;
        i_ln2g = 8; i_ln2b = 9; i_attnw = 10;
        i_l11w = 11; i_l11b = 12; i_ln11g = 13; i_ln11b = 14; i_l12w = 15; i_l12b = 16;
        i_l21w = 17; i_l21b = 18; i_ln21g = 19; i_ln21b = 20; i_l22w = 21; i_l22b = 22;
        i_l3w = 23;  i_l3b = 24;
    } else {
        i_alpha = 4; i_fcw = 5;
        i_ln2g = 6;  i_ln2b = 7; i_attnw = 8;
        i_l11w = 9;  i_l11b = 10; i_ln11g = 11; i_ln11b = 12; i_l12w = 13; i_l12b = 14;
        i_l21w = 15; i_l21b = 16; i_ln21g = 17; i_ln21b = 18; i_l22w = 19; i_l22b = 20;
        i_l3w = 21;  i_l3b = 22;  i_src = 23;   i_dst = 24;
    }

    const float* feat  = (const float*)d_in[0];
    const float* up    = (const float*)d_in[1];
    const float* dn    = (const float*)d_in[2];
    const float* dist  = (const float*)d_in[3];
    const float* alpha = (const float*)d_in[i_alpha];
    const int*   src   = (const int*)d_in[i_src];
    const int*   dst   = (const int*)d_in[i_dst];
    float* out = (float*)d_out;

    prep_kernel<<<1, 256>>>((const float*)d_in[i_ln2g],
                            (const float*)d_in[i_ln2b],
                            (const float*)d_in[i_attnw]);

    init_kernel<<<(NB + 255) / 256, 256>>>(out);

    node_kernel<<<NB / 128, 128>>>(feat, (const float*)d_in[i_fcw]);

    FP p;
    p.up = up; p.dn = dn; p.dist = dist; p.alpha = alpha; p.feat = feat;
    p.src = src; p.dst = dst;
    p.w1u = (const float*)d_in[i_l11w]; p.b1u = (const float*)d_in[i_l11b];
    p.lgu = (const float*)d_in[i_ln11g]; p.lbu = (const float*)d_in[i_ln11b];
    p.w2u = (const float*)d_in[i_l12w]; p.b2u = (const float*)d_in[i_l12b];
    p.w1d = (const float*)d_in[i_l21w]; p.b1d = (const float*)d_in[i_l21b];
    p.lgd = (const float*)d_in[i_ln21g]; p.lbd = (const float*)d_in[i_ln21b];
    p.w2d = (const float*)d_in[i_l22w]; p.b2d = (const float*)d_in[i_l22b];
    p.l3w = (const float*)d_in[i_l3w];  p.l3b = (const float*)d_in[i_l3b];

    fused_kernel<<<(EB / 2) / 256, 256>>>(p);

    edge3_kernel<<<EB / 256, 256>>>(src, dst, out);
}

// round 12
// speedup vs baseline: 1.9226x; 1.0435x over previous
#include <cuda_runtime.h>
#include <math.h>

// ---------------- problem constants ----------------
constexpr int N_NODES = 10000;
constexpr int N_EDGES = 160000;
constexpr int B       = 8;
constexpr int T_IN    = 12;
constexpr int HP      = 64;
constexpr int HV      = 32;
constexpr int HVP     = HV / 2;       // 16 hidden-unit pairs
constexpr int CDIM    = 2 * HP + 1;   // 129
constexpr int NB      = N_NODES * B;  // 80000
constexpr int EB      = N_EDGES * B;  // 1280000

// ---------------- device scratch (static; no allocation) ----------------
__device__ float4 g_node[NB];     // per (node,b): P, R, S, Q
__device__ float  g_att[EB];      // ex = exp(a)
__device__ float  g_dsum[EB];     // sum_k diff*feature[src]
__device__ float  g_den[NB];      // softmax denominator
__device__ float  g_gw[CDIM];     // ln2_g * attn_w
__device__ float  g_GC[2];        // [0]=sum(g*w), [1]=sum(b*w)

// ---------------- packed f32x2 helpers ----------------
using U64 = unsigned long long;

__device__ __forceinline__ void ffma2_acc(U64& c, U64 a, U64 b) {
    asm("fma.rn.f32x2 %0, %1, %2, %0;" : "+l"(c) : "l"(a), "l"(b));
}
__device__ __forceinline__ void add2_acc(U64& c, U64 a) {
    asm("add.rn.f32x2 %0, %0, %1;" : "+l"(c) : "l"(a));
}
__device__ __forceinline__ U64 mul2(U64 a, U64 b) {
    U64 d;
    asm("mul.rn.f32x2 %0, %1, %2;" : "=l"(d) : "l"(a), "l"(b));
    return d;
}
__device__ __forceinline__ U64 pack2(float lo, float hi) {
    U64 d;
    asm("mov.b64 %0, {%1, %2};" : "=l"(d) : "f"(lo), "f"(hi));
    return d;
}
__device__ __forceinline__ void unpack2(U64 v, float& lo, float& hi) {
    asm("mov.b64 {%0, %1}, %2;" : "=f"(lo), "=f"(hi) : "l"(v));
}
__device__ __forceinline__ float f4c(float4 v, int c) {
    return c == 0 ? v.x : c == 1 ? v.y : c == 2 ? v.z : v.w;
}

// ---------------- prep: gw = ln2_g*attn_w; G = sum(gw); C = sum(ln2_b*attn_w) --------
__global__ void prep_kernel(const float* __restrict__ ln2g,
                            const float* __restrict__ ln2b,
                            const float* __restrict__ attnw) {
    __shared__ float sG[256];
    __shared__ float sC[256];
    int t = threadIdx.x;
    float gv = 0.f, cv = 0.f;
    if (t < CDIM) {
        float w = attnw[t];
        gv = ln2g[t] * w;
        cv = ln2b[t] * w;
        g_gw[t] = gv;
    }
    sG[t] = gv; sC[t] = cv;
    __syncthreads();
    for (int s = 128; s > 0; s >>= 1) {
        if (t < s) { sG[t] += sG[t + s]; sC[t] += sC[t + s]; }
        __syncthreads();
    }
    if (t == 0) { g_GC[0] = sG[0]; g_GC[1] = sC[0]; }
}

// ---------------- init: zero pred, den ----------------
__global__ void init_kernel(float* __restrict__ out) {
    int t = blockIdx.x * blockDim.x + threadIdx.x;
    if (t < NB) {
        out[t]   = 0.f;
        g_den[t] = 0.f;
    }
}

// ---------------- node kernel: fold z into (P,R,S,Q) ----------------
__global__ __launch_bounds__(128)
void node_kernel(const float* __restrict__ feat,
                 const float* __restrict__ fcw) {
    __shared__ float sw[HP * T_IN];   // 768
    __shared__ float sgw[2 * HP];     // 128
    int tid = threadIdx.x;
    for (int i = tid; i < HP * T_IN; i += blockDim.x) sw[i]  = fcw[i];
    for (int i = tid; i < 2 * HP;    i += blockDim.x) sgw[i] = g_gw[i];
    __syncthreads();

    int t = blockIdx.x * blockDim.x + tid;
    if (t >= NB) return;

    float fr[T_IN];
    {
        const float4* f4 = reinterpret_cast<const float4*>(feat) + (size_t)t * 3;
        float4 a0 = f4[0], a1 = f4[1], a2 = f4[2];
        fr[0]=a0.x; fr[1]=a0.y; fr[2]=a0.z;  fr[3]=a0.w;
        fr[4]=a1.x; fr[5]=a1.y; fr[6]=a1.z;  fr[7]=a1.w;
        fr[8]=a2.x; fr[9]=a2.y; fr[10]=a2.z; fr[11]=a2.w;
    }

    float P = 0.f, R = 0.f, S = 0.f, Q = 0.f;
#pragma unroll
    for (int h = 0; h < HP; ++h) {
        float z = 0.f;
#pragma unroll
        for (int k = 0; k < T_IN; ++k) z = fmaf(sw[h * T_IN + k], fr[k], z);
        P = fmaf(z, sgw[h], P);
        R = fmaf(z, sgw[HP + h], R);
        S += z;
        Q = fmaf(z, z, Q);
    }
    g_node[t] = make_float4(P, R, S, Q);
}

// ---------------- velocity branch: 4 items per thread-pair, half hidden each --------
// returns sigmoid outputs for this thread's 2 phase-3 items (local items 2par, 2par+1)
__device__ __forceinline__ float2 vbranch4(
    const ulonglong2* __restrict__ swt4,   // [k*8 + jj] pair-of-pairs
    const U64* __restrict__ sb1v,
    const U64* __restrict__ slgv,
    const U64* __restrict__ slbv,
    const float2* __restrict__ sw2p,
    float b2,
    const float* __restrict__ inp, size_t base /* item base (4 items) */,
    int par /* tid&1 */) {

    // load 4 items' inputs (lanes overlap; warp coalescer dedups sectors)
    float4 in4[12];
    {
        const float4* f4 = reinterpret_cast<const float4*>(inp) + base * 3;
#pragma unroll
        for (int v = 0; v < 12; ++v) in4[v] = f4[v];
    }

    int P8 = par * 8;            // this thread's first hidden pair
    U64 h[4][8];
#pragma unroll
    for (int jl = 0; jl < 8; ++jl) {
        U64 bb = sb1v[P8 + jl];
        h[0][jl] = bb; h[1][jl] = bb; h[2][jl] = bb; h[3][jl] = bb;
    }

#pragma unroll
    for (int k = 0; k < T_IN; ++k) {
        ulonglong2 w0 = swt4[k * 8 + par * 4 + 0];
        ulonglong2 w1 = swt4[k * 8 + par * 4 + 1];
        ulonglong2 w2 = swt4[k * 8 + par * 4 + 2];
        ulonglong2 w3 = swt4[k * 8 + par * 4 + 3];
#pragma unroll
        for (int i = 0; i < 4; ++i) {
            float xf = f4c(in4[i * 3 + (k >> 2)], k & 3);
            U64 x = pack2(xf, xf);
            ffma2_acc(h[i][0], w0.x, x); ffma2_acc(h[i][1], w0.y, x);
            ffma2_acc(h[i][2], w1.x, x); ffma2_acc(h[i][3], w1.y, x);
            ffma2_acc(h[i][4], w2.x, x); ffma2_acc(h[i][5], w2.y, x);
            ffma2_acc(h[i][6], w3.x, x); ffma2_acc(h[i][7], w3.y, x);
        }
    }

    // partial LN stats over own 16 hidden, complete via partner exchange
    U64 nm2[4], iv2[4];
#pragma unroll
    for (int i = 0; i < 4; ++i) {
        U64 s = h[i][0];
        U64 q = pack2(0.f, 0.f);
        ffma2_acc(q, h[i][0], h[i][0]);
#pragma unroll
        for (int jl = 1; jl < 8; ++jl) {
            add2_acc(s, h[i][jl]);
            ffma2_acc(q, h[i][jl], h[i][jl]);
        }
        float sa, sb, qa, qb;
        unpack2(s, sa, sb); unpack2(q, qa, qb);
        float ps = sa + sb, pq = qa + qb;
        ps += __shfl_xor_sync(0xffffffffu, ps, 1);
        pq += __shfl_xor_sync(0xffffffffu, pq, 1);
        float m  = ps * (1.0f / HV);
        float iv = rsqrtf(fmaf(-m, m, pq * (1.0f / HV)) + 1e-5f);
        nm2[i] = pack2(-m, -m);
        iv2[i] = pack2(iv, iv);
    }

    // epilogue: partial dot over own hidden, complete via exchange
    float sp0 = 0.f, sp1 = 0.f, sp2 = 0.f, sp3 = 0.f;
#pragma unroll
    for (int jl = 0; jl < 8; ++jl) {
        U64 g  = slgv[P8 + jl];
        U64 bb = slbv[P8 + jl];
        float2 w2v = sw2p[P8 + jl];
        float ya, yb;

        add2_acc(h[0][jl], nm2[0]);
        { U64 sc = mul2(iv2[0], g); U64 y = bb; ffma2_acc(y, h[0][jl], sc);
          unpack2(y, ya, yb); ya = fmaxf(ya, 0.f); yb = fmaxf(yb, 0.f);
          sp0 = fmaf(ya, w2v.x, sp0); sp0 = fmaf(yb, w2v.y, sp0); }
        add2_acc(h[1][jl], nm2[1]);
        { U64 sc = mul2(iv2[1], g); U64 y = bb; ffma2_acc(y, h[1][jl], sc);
          unpack2(y, ya, yb); ya = fmaxf(ya, 0.f); yb = fmaxf(yb, 0.f);
          sp1 = fmaf(ya, w2v.x, sp1); sp1 = fmaf(yb, w2v.y, sp1); }
        add2_acc(h[2][jl], nm2[2]);
        { U64 sc = mul2(iv2[2], g); U64 y = bb; ffma2_acc(y, h[2][jl], sc);
          unpack2(y, ya, yb); ya = fmaxf(ya, 0.f); yb = fmaxf(yb, 0.f);
          sp2 = fmaf(ya, w2v.x, sp2); sp2 = fmaf(yb, w2v.y, sp2); }
        add2_acc(h[3][jl], nm2[3]);
        { U64 sc = mul2(iv2[3], g); U64 y = bb; ffma2_acc(y, h[3][jl], sc);
          unpack2(y, ya, yb); ya = fmaxf(ya, 0.f); yb = fmaxf(yb, 0.f);
          sp3 = fmaf(ya, w2v.x, sp3); sp3 = fmaf(yb, w2v.y, sp3); }
    }
    float s0 = sp0 + __shfl_xor_sync(0xffffffffu, sp0, 1) + b2;
    float s1 = sp1 + __shfl_xor_sync(0xffffffffu, sp1, 1) + b2;
    float s2 = sp2 + __shfl_xor_sync(0xffffffffu, sp2, 1) + b2;
    float s3 = sp3 + __shfl_xor_sync(0xffffffffu, sp3, 1) + b2;

    float sA = par ? s2 : s0;      // local item 2*par
    float sB = par ? s3 : s1;      // local item 2*par+1
    float2 o;
    o.x = __fdividef(1.0f, 1.0f + __expf(-sA));
    o.y = __fdividef(1.0f, 1.0f + __expf(-sB));
    return o;
}

// ---------------- fused kernel: vel-up + vel-dn + edge attention/diffusion ----------
struct FP {
    const float *up, *dn, *dist, *alpha, *feat;
    const int   *src, *dst;
    const float *w1u, *b1u, *lgu, *lbu, *w2u, *b2u;
    const float *w1d, *b1d, *lgd, *lbd, *w2d, *b2d;
    const float *l3w, *l3b;
};

__global__ __launch_bounds__(128)
void fused_kernel(FP p) {
    __shared__ __align__(16) float2 sWU[T_IN * HVP];   // 1.5 KB
    __shared__ __align__(16) float2 sWD[T_IN * HVP];   // 1.5 KB
    __shared__ __align__(8)  float2 sb1U[HVP], slgU[HVP], slbU[HVP], sw2U[HVP];
    __shared__ __align__(8)  float2 sb1D[HVP], slgD[HVP], slbD[HVP], sw2D[HVP];
    __shared__ float sb2s[2];
    __shared__ float c[7];

    int tid = threadIdx.x;
    for (int i = tid; i < T_IN * HVP; i += 128) {
        int k  = i >> 4;
        int jp = i & 15;
        sWU[i] = make_float2(p.w1u[(2*jp)*T_IN + k], p.w1u[(2*jp+1)*T_IN + k]);
        sWD[i] = make_float2(p.w1d[(2*jp)*T_IN + k], p.w1d[(2*jp+1)*T_IN + k]);
    }
    if (tid < HVP) {
        int jp = tid;
        sb1U[jp] = make_float2(p.b1u[2*jp], p.b1u[2*jp+1]);
        slgU[jp] = make_float2(p.lgu[2*jp], p.lgu[2*jp+1]);
        slbU[jp] = make_float2(p.lbu[2*jp], p.lbu[2*jp+1]);
        sw2U[jp] = make_float2(p.w2u[2*jp], p.w2u[2*jp+1]);
    } else if (tid < 2 * HVP) {
        int jp = tid - HVP;
        sb1D[jp] = make_float2(p.b1d[2*jp], p.b1d[2*jp+1]);
        slgD[jp] = make_float2(p.lgd[2*jp], p.lgd[2*jp+1]);
        slbD[jp] = make_float2(p.lbd[2*jp], p.lbd[2*jp+1]);
        sw2D[jp] = make_float2(p.w2d[2*jp], p.w2d[2*jp+1]);
    } else if (tid == 2 * HVP) {
        sb2s[0] = p.b2u[0]; sb2s[1] = p.b2d[0];
        c[0] = p.l3w[0]; c[1] = p.l3w[1]; c[2] = p.l3w[2]; c[3] = p.l3b[0];
        c[4] = g_gw[128]; c[5] = g_GC[0]; c[6] = g_GC[1];
    }
    __syncthreads();

    int    gid  = blockIdx.x * 128 + tid;        // gid < EB/2
    int    par  = tid & 1;
    size_t base = (size_t)(gid >> 1) * 4;        // item base for the thread pair

    // phase 1 + 2: velocity branches (this thread's 2 items = 2*gid, 2*gid+1)
    float2 xu = vbranch4(reinterpret_cast<const ulonglong2*>(sWU),
                         reinterpret_cast<const U64*>(sb1U),
                         reinterpret_cast<const U64*>(slgU),
                         reinterpret_cast<const U64*>(slbU),
                         sw2U, sb2s[0], p.up, base, par);
    float2 xd = vbranch4(reinterpret_cast<const ulonglong2*>(sWD),
                         reinterpret_cast<const U64*>(sb1D),
                         reinterpret_cast<const U64*>(slgD),
                         reinterpret_cast<const U64*>(slbD),
                         sw2D, sb2s[1], p.dn, base, par);

    // phase 3: attention + diffusion, items 2*gid, 2*gid+1 (same edge)
    size_t t = (size_t)gid;
    int e  = (int)(t >> 2);
    int b0 = ((int)t & 3) * 2;

    float al   = p.alpha[e];
    float dste = p.dist[e];
    float alc  = fminf(fmaxf(al, 0.f), 1.f);
    int se = p.src[e];
    int de = p.dst[e];

    float f0[T_IN], f1[T_IN];
    {
        const float4* f4 = reinterpret_cast<const float4*>(p.feat)
                           + ((size_t)se * B + b0) * 3;
        float4 q0 = f4[0], q1 = f4[1], q2 = f4[2];
        float4 q3 = f4[3], q4 = f4[4], q5 = f4[5];
        f0[0]=q0.x; f0[1]=q0.y; f0[2]=q0.z;  f0[3]=q0.w;
        f0[4]=q1.x; f0[5]=q1.y; f0[6]=q1.z;  f0[7]=q1.w;
        f0[8]=q2.x; f0[9]=q2.y; f0[10]=q2.z; f0[11]=q2.w;
        f1[0]=q3.x; f1[1]=q3.y; f1[2]=q3.z;  f1[3]=q3.w;
        f1[4]=q4.x; f1[5]=q4.y; f1[6]=q4.z;  f1[7]=q4.w;
        f1[8]=q5.x; f1[9]=q5.y; f1[10]=q5.z; f1[11]=q5.w;
    }
    const float4* nsrc = &g_node[se * B + b0];
    const float4* ndst = &g_node[de * B + b0];

    float2 exo, dso;
#pragma unroll
    for (int i = 0; i < 2; ++i) {
        float xup = (i == 0) ? xu.x : xu.y;
        float xdn = (i == 0) ? xd.x : xd.y;
        const float* f = (i == 0) ? f0 : f1;

        float xv = c[0] * xup + c[1] * xdn + c[2] * al + c[3];
        float v = (xv > 0.f) ? (xv + __logf(1.0f + __expf(-xv)))
                             : __logf(1.0f + __expf(xv));
        v = fminf(v, 3.0f);
        float Tt = __fdividef(dste, v + 1e-5f);

        float Tidx = fminf(fmaxf(rintf(Tt * 0.1f), 0.0f), 11.0f);
        int   n    = T_IN - (int)Tidx;              // 1..12
        float F    = __fdividef(1.0f, 1.0f + alc * Tt);
        float omF  = 1.0f - F;

        float acc = 0.f, pw = 0.f;
#pragma unroll
        for (int k = T_IN - 1; k >= 0; --k) {
            if (k == n - 1) pw = F;
            if (k <= n - 1) { acc = fmaf(pw, f[k], acc); pw *= omF; }
        }

        float4 ns = nsrc[i];
        float4 nd = ndst[i];
        float Ssum = ns.z + nd.z + Tt;
        float m    = Ssum * (1.0f / 129.0f);
        float q    = ns.w + nd.w + Tt * Tt;
        float var  = q * (1.0f / 129.0f) - m * m;
        float dot  = ns.x + nd.y + Tt * c[4];
        float a    = (dot - m * c[5]) * rsqrtf(var + 1e-5f) + c[6];
        a = (a >= 0.f) ? a : 0.01f * a;             // leaky_relu

        float ex = __expf(a);
        if (i == 0) { exo.x = ex; dso.x = acc; }
        else        { exo.y = ex; dso.y = acc; }
        atomicAdd(&g_den[se * B + b0 + i], ex);
    }

    reinterpret_cast<float2*>(g_att)[t]  = exo;
    reinterpret_cast<float2*>(g_dsum)[t] = dso;
}

// ---------------- edge pass 3: pred[dst] += ex/den[src] * dsum ----------------
__global__ __launch_bounds__(256)
void edge3_kernel(const int* __restrict__ src, const int* __restrict__ dst,
                  float* __restrict__ out) {
    int t = blockIdx.x * 256 + threadIdx.x;
    if (t >= EB) return;
    int e = t >> 3, b = t & 7;
    int se = src[e];
    int de = dst[e];
    float val = __fdividef(g_att[t], g_den[se * B + b]) * g_dsum[t];
    atomicAdd(&out[de * B + b], val);
}

// ---------------- launch ----------------
extern "C" void kernel_launch(void* const* d_in, const int* in_sizes, int n_in,
                              void* d_out, int out_size) {
    bool sig_order = (n_in >= 6 && in_sizes[5] == HP * T_IN);   // fc_w=768 at idx 5

    int i_src, i_dst, i_alpha, i_fcw, i_ln2g, i_ln2b, i_attnw;
    int i_l11w, i_l11b, i_ln11g, i_ln11b, i_l12w, i_l12b;
    int i_l21w, i_l21b, i_ln21g, i_ln21b, i_l22w, i_l22b, i_l3w, i_l3b;

    if (!sig_order) {
        i_src = 4;  i_dst = 5;  i_alpha = 6;  i_fcw = 7;
        i_ln2g = 8; i_ln2b = 9; i_attnw = 10;
        i_l11w = 11; i_l11b = 12; i_ln11g = 13; i_ln11b = 14; i_l12w = 15; i_l12b = 16;
        i_l21w = 17; i_l21b = 18; i_ln21g = 19; i_ln21b = 20; i_l22w = 21; i_l22b = 22;
        i_l3w = 23;  i_l3b = 24;
    } else {
        i_alpha = 4; i_fcw = 5;
        i_ln2g = 6;  i_ln2b = 7; i_attnw = 8;
        i_l11w = 9;  i_l11b = 10; i_ln11g = 11; i_ln11b = 12; i_l12w = 13; i_l12b = 14;
        i_l21w = 15; i_l21b = 16; i_ln21g = 17; i_ln21b = 18; i_l22w = 19; i_l22b = 20;
        i_l3w = 21;  i_l3b = 22;  i_src = 23;   i_dst = 24;
    }

    const float* feat  = (const float*)d_in[0];
    const float* up    = (const float*)d_in[1];
    const float* dn    = (const float*)d_in[2];
    const float* dist  = (const float*)d_in[3];
    const float* alpha = (const float*)d_in[i_alpha];
    const int*   src   = (const int*)d_in[i_src];
    const int*   dst   = (const int*)d_in[i_dst];
    float* out = (float*)d_out;

    prep_kernel<<<1, 256>>>((const float*)d_in[i_ln2g],
                            (const float*)d_in[i_ln2b],
                            (const float*)d_in[i_attnw]);

    init_kernel<<<(NB + 255) / 256, 256>>>(out);

    node_kernel<<<NB / 128, 128>>>(feat, (const float*)d_in[i_fcw]);

    FP p;
    p.up = up; p.dn = dn; p.dist = dist; p.alpha = alpha; p.feat = feat;
    p.src = src; p.dst = dst;
    p.w1u = (const float*)d_in[i_l11w]; p.b1u = (const float*)d_in[i_l11b];
    p.lgu = (const float*)d_in[i_ln11g]; p.lbu = (const float*)d_in[i_ln11b];
    p.w2u = (const float*)d_in[i_l12w]; p.b2u = (const float*)d_in[i_l12b];
    p.w1d = (const float*)d_in[i_l21w]; p.b1d = (const float*)d_in[i_l21b];
    p.lgd = (const float*)d_in[i_ln21g]; p.lbd = (const float*)d_in[i_ln21b];
    p.w2d = (const float*)d_in[i_l22w]; p.b2d = (const float*)d_in[i_l22b];
    p.l3w = (const float*)d_in[i_l3w];  p.l3b = (const float*)d_in[i_l3b];

    fused_kernel<<<(EB / 2) / 128, 128>>>(p);

    edge3_kernel<<<EB / 256, 256>>>(src, dst, out);
}

// round 13
// speedup vs baseline: 1.9260x; 1.0017x over previous
#include <cuda_runtime.h>
#include <math.h>

// ---------------- problem constants ----------------
constexpr int N_NODES = 10000;
constexpr int N_EDGES = 160000;
constexpr int B       = 8;
constexpr int T_IN    = 12;
constexpr int HP      = 64;
constexpr int HV      = 32;
constexpr int HVP     = HV / 2;       // 16 hidden-unit pairs
constexpr int CDIM    = 2 * HP + 1;   // 129
constexpr int NB      = N_NODES * B;  // 80000
constexpr int EB      = N_EDGES * B;  // 1280000

// ---------------- device scratch (static; no allocation) ----------------
__device__ float4 g_node[NB];     // per (node,b): P, R, S, Q
__device__ float  g_att[EB];      // ex = exp(a)
__device__ float  g_dsum[EB];     // sum_k diff*feature[src]
__device__ float  g_den[NB];      // softmax denominator
__device__ float  g_gw[CDIM];     // ln2_g * attn_w
__device__ float  g_GC[2];        // [0]=sum(g*w), [1]=sum(b*w)

// ---------------- packed f32x2 helpers ----------------
using U64 = unsigned long long;

__device__ __forceinline__ void ffma2_acc(U64& c, U64 a, U64 b) {
    asm("fma.rn.f32x2 %0, %1, %2, %0;" : "+l"(c) : "l"(a), "l"(b));
}
__device__ __forceinline__ void add2_acc(U64& c, U64 a) {
    asm("add.rn.f32x2 %0, %0, %1;" : "+l"(c) : "l"(a));
}
__device__ __forceinline__ U64 mul2(U64 a, U64 b) {
    U64 d;
    asm("mul.rn.f32x2 %0, %1, %2;" : "=l"(d) : "l"(a), "l"(b));
    return d;
}
__device__ __forceinline__ U64 pack2(float lo, float hi) {
    U64 d;
    asm("mov.b64 %0, {%1, %2};" : "=l"(d) : "f"(lo), "f"(hi));
    return d;
}
__device__ __forceinline__ void unpack2(U64 v, float& lo, float& hi) {
    asm("mov.b64 {%0, %1}, %2;" : "=f"(lo), "=f"(hi) : "l"(v));
}
__device__ __forceinline__ float f4c(float4 v, int c) {
    return c == 0 ? v.x : c == 1 ? v.y : c == 2 ? v.z : v.w;
}

// ---------------- prep: gw = ln2_g*attn_w; G = sum(gw); C = sum(ln2_b*attn_w) --------
__global__ void prep_kernel(const float* __restrict__ ln2g,
                            const float* __restrict__ ln2b,
                            const float* __restrict__ attnw) {
    __shared__ float sG[256];
    __shared__ float sC[256];
    int t = threadIdx.x;
    float gv = 0.f, cv = 0.f;
    if (t < CDIM) {
        float w = attnw[t];
        gv = ln2g[t] * w;
        cv = ln2b[t] * w;
        g_gw[t] = gv;
    }
    sG[t] = gv; sC[t] = cv;
    __syncthreads();
    for (int s = 128; s > 0; s >>= 1) {
        if (t < s) { sG[t] += sG[t + s]; sC[t] += sC[t + s]; }
        __syncthreads();
    }
    if (t == 0) { g_GC[0] = sG[0]; g_GC[1] = sC[0]; }
}

// ---------------- init: zero pred, den ----------------
__global__ void init_kernel(float* __restrict__ out) {
    int t = blockIdx.x * blockDim.x + threadIdx.x;
    if (t < NB) {
        out[t]   = 0.f;
        g_den[t] = 0.f;
    }
}

// ---------------- node kernel: fold z into (P,R,S,Q) ----------------
__global__ __launch_bounds__(128)
void node_kernel(const float* __restrict__ feat,
                 const float* __restrict__ fcw) {
    __shared__ float sw[HP * T_IN];   // 768
    __shared__ float sgw[2 * HP];     // 128
    int tid = threadIdx.x;
    for (int i = tid; i < HP * T_IN; i += blockDim.x) sw[i]  = fcw[i];
    for (int i = tid; i < 2 * HP;    i += blockDim.x) sgw[i] = g_gw[i];
    __syncthreads();

    int t = blockIdx.x * blockDim.x + tid;
    if (t >= NB) return;

    float fr[T_IN];
    {
        const float4* f4 = reinterpret_cast<const float4*>(feat) + (size_t)t * 3;
        float4 a0 = f4[0], a1 = f4[1], a2 = f4[2];
        fr[0]=a0.x; fr[1]=a0.y; fr[2]=a0.z;  fr[3]=a0.w;
        fr[4]=a1.x; fr[5]=a1.y; fr[6]=a1.z;  fr[7]=a1.w;
        fr[8]=a2.x; fr[9]=a2.y; fr[10]=a2.z; fr[11]=a2.w;
    }

    float P = 0.f, R = 0.f, S = 0.f, Q = 0.f;
#pragma unroll
    for (int h = 0; h < HP; ++h) {
        float z = 0.f;
#pragma unroll
        for (int k = 0; k < T_IN; ++k) z = fmaf(sw[h * T_IN + k], fr[k], z);
        P = fmaf(z, sgw[h], P);
        R = fmaf(z, sgw[HP + h], R);
        S += z;
        Q = fmaf(z, z, Q);
    }
    g_node[t] = make_float4(P, R, S, Q);
}

// ---------------- velocity branch: 4 items per thread-pair, half hidden each --------
// k-loop chunked 3x4 to keep only 16 input regs live (occupancy lever)
__device__ __forceinline__ float2 vbranch4(
    const ulonglong2* __restrict__ swt4,   // [k*8 + jj] pair-of-pairs
    const U64* __restrict__ sb1v,
    const U64* __restrict__ slgv,
    const U64* __restrict__ slbv,
    const float2* __restrict__ sw2p,
    float b2,
    const float* __restrict__ inp, size_t base /* item base (4 items) */,
    int par /* tid&1 */) {

    const float4* f4 = reinterpret_cast<const float4*>(inp) + base * 3;

    int P8 = par * 8;            // this thread's first hidden pair
    U64 h[4][8];
#pragma unroll
    for (int jl = 0; jl < 8; ++jl) {
        U64 bb = sb1v[P8 + jl];
        h[0][jl] = bb; h[1][jl] = bb; h[2][jl] = bb; h[3][jl] = bb;
    }

#pragma unroll
    for (int cc = 0; cc < 3; ++cc) {                 // 3 chunks of 4 k's
        float4 v0 = f4[0 * 3 + cc];
        float4 v1 = f4[1 * 3 + cc];
        float4 v2 = f4[2 * 3 + cc];
        float4 v3 = f4[3 * 3 + cc];
#pragma unroll
        for (int kk = 0; kk < 4; ++kk) {
            int k = cc * 4 + kk;
            ulonglong2 w0 = swt4[k * 8 + par * 4 + 0];
            ulonglong2 w1 = swt4[k * 8 + par * 4 + 1];
            ulonglong2 w2 = swt4[k * 8 + par * 4 + 2];
            ulonglong2 w3 = swt4[k * 8 + par * 4 + 3];

            float xf; U64 x;
            xf = f4c(v0, kk); x = pack2(xf, xf);
            ffma2_acc(h[0][0], w0.x, x); ffma2_acc(h[0][1], w0.y, x);
            ffma2_acc(h[0][2], w1.x, x); ffma2_acc(h[0][3], w1.y, x);
            ffma2_acc(h[0][4], w2.x, x); ffma2_acc(h[0][5], w2.y, x);
            ffma2_acc(h[0][6], w3.x, x); ffma2_acc(h[0][7], w3.y, x);
            xf = f4c(v1, kk); x = pack2(xf, xf);
            ffma2_acc(h[1][0], w0.x, x); ffma2_acc(h[1][1], w0.y, x);
            ffma2_acc(h[1][2], w1.x, x); ffma2_acc(h[1][3], w1.y, x);
            ffma2_acc(h[1][4], w2.x, x); ffma2_acc(h[1][5], w2.y, x);
            ffma2_acc(h[1][6], w3.x, x); ffma2_acc(h[1][7], w3.y, x);
            xf = f4c(v2, kk); x = pack2(xf, xf);
            ffma2_acc(h[2][0], w0.x, x); ffma2_acc(h[2][1], w0.y, x);
            ffma2_acc(h[2][2], w1.x, x); ffma2_acc(h[2][3], w1.y, x);
            ffma2_acc(h[2][4], w2.x, x); ffma2_acc(h[2][5], w2.y, x);
            ffma2_acc(h[2][6], w3.x, x); ffma2_acc(h[2][7], w3.y, x);
            xf = f4c(v3, kk); x = pack2(xf, xf);
            ffma2_acc(h[3][0], w0.x, x); ffma2_acc(h[3][1], w0.y, x);
            ffma2_acc(h[3][2], w1.x, x); ffma2_acc(h[3][3], w1.y, x);
            ffma2_acc(h[3][4], w2.x, x); ffma2_acc(h[3][5], w2.y, x);
            ffma2_acc(h[3][6], w3.x, x); ffma2_acc(h[3][7], w3.y, x);
        }
    }

    // partial LN stats over own 16 hidden, complete via partner exchange
    U64 nm2[4], iv2[4];
#pragma unroll
    for (int i = 0; i < 4; ++i) {
        U64 s = h[i][0];
        U64 q = pack2(0.f, 0.f);
        ffma2_acc(q, h[i][0], h[i][0]);
#pragma unroll
        for (int jl = 1; jl < 8; ++jl) {
            add2_acc(s, h[i][jl]);
            ffma2_acc(q, h[i][jl], h[i][jl]);
        }
        float sa, sb, qa, qb;
        unpack2(s, sa, sb); unpack2(q, qa, qb);
        float ps = sa + sb, pq = qa + qb;
        ps += __shfl_xor_sync(0xffffffffu, ps, 1);
        pq += __shfl_xor_sync(0xffffffffu, pq, 1);
        float m  = ps * (1.0f / HV);
        float iv = rsqrtf(fmaf(-m, m, pq * (1.0f / HV)) + 1e-5f);
        nm2[i] = pack2(-m, -m);
        iv2[i] = pack2(iv, iv);
    }

    // epilogue: partial dot over own hidden, complete via exchange
    float sp0 = 0.f, sp1 = 0.f, sp2 = 0.f, sp3 = 0.f;
#pragma unroll
    for (int jl = 0; jl < 8; ++jl) {
        U64 g  = slgv[P8 + jl];
        U64 bb = slbv[P8 + jl];
        float2 w2v = sw2p[P8 + jl];
        float ya, yb;

        add2_acc(h[0][jl], nm2[0]);
        { U64 sc = mul2(iv2[0], g); U64 y = bb; ffma2_acc(y, h[0][jl], sc);
          unpack2(y, ya, yb); ya = fmaxf(ya, 0.f); yb = fmaxf(yb, 0.f);
          sp0 = fmaf(ya, w2v.x, sp0); sp0 = fmaf(yb, w2v.y, sp0); }
        add2_acc(h[1][jl], nm2[1]);
        { U64 sc = mul2(iv2[1], g); U64 y = bb; ffma2_acc(y, h[1][jl], sc);
          unpack2(y, ya, yb); ya = fmaxf(ya, 0.f); yb = fmaxf(yb, 0.f);
          sp1 = fmaf(ya, w2v.x, sp1); sp1 = fmaf(yb, w2v.y, sp1); }
        add2_acc(h[2][jl], nm2[2]);
        { U64 sc = mul2(iv2[2], g); U64 y = bb; ffma2_acc(y, h[2][jl], sc);
          unpack2(y, ya, yb); ya = fmaxf(ya, 0.f); yb = fmaxf(yb, 0.f);
          sp2 = fmaf(ya, w2v.x, sp2); sp2 = fmaf(yb, w2v.y, sp2); }
        add2_acc(h[3][jl], nm2[3]);
        { U64 sc = mul2(iv2[3], g); U64 y = bb; ffma2_acc(y, h[3][jl], sc);
          unpack2(y, ya, yb); ya = fmaxf(ya, 0.f); yb = fmaxf(yb, 0.f);
          sp3 = fmaf(ya, w2v.x, sp3); sp3 = fmaf(yb, w2v.y, sp3); }
    }
    float s0 = sp0 + __shfl_xor_sync(0xffffffffu, sp0, 1) + b2;
    float s1 = sp1 + __shfl_xor_sync(0xffffffffu, sp1, 1) + b2;
    float s2 = sp2 + __shfl_xor_sync(0xffffffffu, sp2, 1) + b2;
    float s3 = sp3 + __shfl_xor_sync(0xffffffffu, sp3, 1) + b2;

    float sA = par ? s2 : s0;      // local item 2*par
    float sB = par ? s3 : s1;      // local item 2*par+1
    float2 o;
    o.x = __fdividef(1.0f, 1.0f + __expf(-sA));
    o.y = __fdividef(1.0f, 1.0f + __expf(-sB));
    return o;
}

// ---------------- fused kernel: vel-up + vel-dn + edge attention/diffusion ----------
struct FP {
    const float *up, *dn, *dist, *alpha, *feat;
    const int   *src, *dst;
    const float *w1u, *b1u, *lgu, *lbu, *w2u, *b2u;
    const float *w1d, *b1d, *lgd, *lbd, *w2d, *b2d;
    const float *l3w, *l3b;
};

__global__ __launch_bounds__(128, 5)
void fused_kernel(FP p) {
    __shared__ __align__(16) float2 sWU[T_IN * HVP];   // 1.5 KB
    __shared__ __align__(16) float2 sWD[T_IN * HVP];   // 1.5 KB
    __shared__ __align__(8)  float2 sb1U[HVP], slgU[HVP], slbU[HVP], sw2U[HVP];
    __shared__ __align__(8)  float2 sb1D[HVP], slgD[HVP], slbD[HVP], sw2D[HVP];
    __shared__ float sb2s[2];
    __shared__ float c[7];

    int tid = threadIdx.x;
    for (int i = tid; i < T_IN * HVP; i += 128) {
        int k  = i >> 4;
        int jp = i & 15;
        sWU[i] = make_float2(p.w1u[(2*jp)*T_IN + k], p.w1u[(2*jp+1)*T_IN + k]);
        sWD[i] = make_float2(p.w1d[(2*jp)*T_IN + k], p.w1d[(2*jp+1)*T_IN + k]);
    }
    if (tid < HVP) {
        int jp = tid;
        sb1U[jp] = make_float2(p.b1u[2*jp], p.b1u[2*jp+1]);
        slgU[jp] = make_float2(p.lgu[2*jp], p.lgu[2*jp+1]);
        slbU[jp] = make_float2(p.lbu[2*jp], p.lbu[2*jp+1]);
        sw2U[jp] = make_float2(p.w2u[2*jp], p.w2u[2*jp+1]);
    } else if (tid < 2 * HVP) {
        int jp = tid - HVP;
        sb1D[jp] = make_float2(p.b1d[2*jp], p.b1d[2*jp+1]);
        slgD[jp] = make_float2(p.lgd[2*jp], p.lgd[2*jp+1]);
        slbD[jp] = make_float2(p.lbd[2*jp], p.lbd[2*jp+1]);
        sw2D[jp] = make_float2(p.w2d[2*jp], p.w2d[2*jp+1]);
    } else if (tid == 2 * HVP) {
        sb2s[0] = p.b2u[0]; sb2s[1] = p.b2d[0];
        c[0] = p.l3w[0]; c[1] = p.l3w[1]; c[2] = p.l3w[2]; c[3] = p.l3b[0];
        c[4] = g_gw[128]; c[5] = g_GC[0]; c[6] = g_GC[1];
    }
    __syncthreads();

    int    gid  = blockIdx.x * 128 + tid;        // gid < EB/2
    int    par  = tid & 1;
    size_t base = (size_t)(gid >> 1) * 4;        // item base for the thread pair

    // phase 1 + 2: velocity branches (this thread's 2 items = 2*gid, 2*gid+1)
    float2 xu = vbranch4(reinterpret_cast<const ulonglong2*>(sWU),
                         reinterpret_cast<const U64*>(sb1U),
                         reinterpret_cast<const U64*>(slgU),
                         reinterpret_cast<const U64*>(slbU),
                         sw2U, sb2s[0], p.up, base, par);
    float2 xd = vbranch4(reinterpret_cast<const ulonglong2*>(sWD),
                         reinterpret_cast<const U64*>(sb1D),
                         reinterpret_cast<const U64*>(slgD),
                         reinterpret_cast<const U64*>(slbD),
                         sw2D, sb2s[1], p.dn, base, par);

    // phase 3: attention + diffusion, items 2*gid, 2*gid+1 (same edge)
    size_t t = (size_t)gid;
    int e  = (int)(t >> 2);
    int b0 = ((int)t & 3) * 2;

    float al   = p.alpha[e];
    float dste = p.dist[e];
    float alc  = fminf(fmaxf(al, 0.f), 1.f);
    int se = p.src[e];
    int de = p.dst[e];

    float f0[T_IN], f1[T_IN];
    {
        const float4* f4 = reinterpret_cast<const float4*>(p.feat)
                           + ((size_t)se * B + b0) * 3;
        float4 q0 = f4[0], q1 = f4[1], q2 = f4[2];
        float4 q3 = f4[3], q4 = f4[4], q5 = f4[5];
        f0[0]=q0.x; f0[1]=q0.y; f0[2]=q0.z;  f0[3]=q0.w;
        f0[4]=q1.x; f0[5]=q1.y; f0[6]=q1.z;  f0[7]=q1.w;
        f0[8]=q2.x; f0[9]=q2.y; f0[10]=q2.z; f0[11]=q2.w;
        f1[0]=q3.x; f1[1]=q3.y; f1[2]=q3.z;  f1[3]=q3.w;
        f1[4]=q4.x; f1[5]=q4.y; f1[6]=q4.z;  f1[7]=q4.w;
        f1[8]=q5.x; f1[9]=q5.y; f1[10]=q5.z; f1[11]=q5.w;
    }
    const float4* nsrc = &g_node[se * B + b0];
    const float4* ndst = &g_node[de * B + b0];

    float2 exo, dso;
#pragma unroll
    for (int i = 0; i < 2; ++i) {
        float xup = (i == 0) ? xu.x : xu.y;
        float xdn = (i == 0) ? xd.x : xd.y;
        const float* f = (i == 0) ? f0 : f1;

        float xv = c[0] * xup + c[1] * xdn + c[2] * al + c[3];
        float v = (xv > 0.f) ? (xv + __logf(1.0f + __expf(-xv)))
                             : __logf(1.0f + __expf(xv));
        v = fminf(v, 3.0f);
        float Tt = __fdividef(dste, v + 1e-5f);

        float Tidx = fminf(fmaxf(rintf(Tt * 0.1f), 0.0f), 11.0f);
        int   n    = T_IN - (int)Tidx;              // 1..12
        float F    = __fdividef(1.0f, 1.0f + alc * Tt);
        float omF  = 1.0f - F;

        float acc = 0.f, pw = 0.f;
#pragma unroll
        for (int k = T_IN - 1; k >= 0; --k) {
            if (k == n - 1) pw = F;
            if (k <= n - 1) { acc = fmaf(pw, f[k], acc); pw *= omF; }
        }

        float4 ns = nsrc[i];
        float4 nd = ndst[i];
        float Ssum = ns.z + nd.z + Tt;
        float m    = Ssum * (1.0f / 129.0f);
        float q    = ns.w + nd.w + Tt * Tt;
        float var  = q * (1.0f / 129.0f) - m * m;
        float dot  = ns.x + nd.y + Tt * c[4];
        float a    = (dot - m * c[5]) * rsqrtf(var + 1e-5f) + c[6];
        a = (a >= 0.f) ? a : 0.01f * a;             // leaky_relu

        float ex = __expf(a);
        if (i == 0) { exo.x = ex; dso.x = acc; }
        else        { exo.y = ex; dso.y = acc; }
        atomicAdd(&g_den[se * B + b0 + i], ex);
    }

    reinterpret_cast<float2*>(g_att)[t]  = exo;
    reinterpret_cast<float2*>(g_dsum)[t] = dso;
}

// ---------------- edge pass 3: pred[dst] += ex/den[src] * dsum ----------------
__global__ __launch_bounds__(256)
void edge3_kernel(const int* __restrict__ src, const int* __restrict__ dst,
                  float* __restrict__ out) {
    int t = blockIdx.x * 256 + threadIdx.x;
    if (t >= EB) return;
    int e = t >> 3, b = t & 7;
    int se = src[e];
    int de = dst[e];
    float val = __fdividef(g_att[t], g_den[se * B + b]) * g_dsum[t];
    atomicAdd(&out[de * B + b], val);
}

// ---------------- launch ----------------
extern "C" void kernel_launch(void* const* d_in, const int* in_sizes, int n_in,
                              void* d_out, int out_size) {
    bool sig_order = (n_in >= 6 && in_sizes[5] == HP * T_IN);   // fc_w=768 at idx 5

    int i_src, i_dst, i_alpha, i_fcw, i_ln2g, i_ln2b, i_attnw;
    int i_l11w, i_l11b, i_ln11g, i_ln11b, i_l12w, i_l12b;
    int i_l21w, i_l21b, i_ln21g, i_ln21b, i_l22w, i_l22b, i_l3w, i_l3b;

    if (!sig_order) {
        i_src = 4;  i_dst = 5;  i_alpha = 6;  i_fcw = 7;
        i_ln2g = 8; i_ln2b = 9; i_attnw = 10;
        i_l11w = 11; i_l11b = 12; i_ln11g = 13; i_ln11b = 14; i_l12w = 15; i_l12b = 16;
        i_l21w = 17; i_l21b = 18; i_ln21g = 19; i_ln21b = 20; i_l22w = 21; i_l22b = 22;
        i_l3w = 23;  i_l3b = 24;
    } else {
        i_alpha = 4; i_fcw = 5;
        i_ln2g = 6;  i_ln2b = 7; i_attnw = 8;
        i_l11w = 9;  i_l11b = 10; i_ln11g = 11; i_ln11b = 12; i_l12w = 13; i_l12b = 14;
        i_l21w = 15; i_l21b = 16; i_ln21g = 17; i_ln21b = 18; i_l22w = 19; i_l22b = 20;
        i_l3w = 21;  i_l3b = 22;  i_src = 23;   i_dst = 24;
    }

    const float* feat  = (const float*)d_in[0];
    const float* up    = (const float*)d_in[1];
    const float* dn    = (const float*)d_in[2];
    const float* dist  = (const float*)d_in[3];
    const float* alpha = (const float*)d_in[i_alpha];
    const int*   src   = (const int*)d_in[i_src];
    const int*   dst   = (const int*)d_in[i_dst];
    float* out = (float*)d_out;

    prep_kernel<<<1, 256>>>((const float*)d_in[i_ln2g],
                            (const float*)d_in[i_ln2b],
                            (const float*)d_in[i_attnw]);

    init_kernel<<<(NB + 255) / 256, 256>>>(out);

    node_kernel<<<NB / 128, 128>>>(feat, (const float*)d_in[i_fcw]);

    FP p;
    p.up = up; p.dn = dn; p.dist = dist; p.alpha = alpha; p.feat = feat;
    p.src = src; p.dst = dst;
    p.w1u = (const float*)d_in[i_l11w]; p.b1u = (const float*)d_in[i_l11b];
    p.lgu = (const float*)d_in[i_ln11g]; p.lbu = (const float*)d_in[i_ln11b];
    p.w2u = (const float*)d_in[i_l12w]; p.b2u = (const float*)d_in[i_l12b];
    p.w1d = (const float*)d_in[i_l21w]; p.b1d = (const float*)d_in[i_l21b];
    p.lgd = (const float*)d_in[i_ln21g]; p.lbd = (const float*)d_in[i_ln21b];
    p.w2d = (const float*)d_in[i_l22w]; p.b2d = (const float*)d_in[i_l22b];
    p.l3w = (const float*)d_in[i_l3w];  p.l3b = (const float*)d_in[i_l3b];

    fused_kernel<<<(EB / 2) / 128, 128>>>(p);

    edge3_kernel<<<EB / 256, 256>>>(src, dst, out);
}